// round 13
// baseline (speedup 1.0000x reference)
#include <cuda_runtime.h>
#include <cuda_fp16.h>
#include <math.h>

#define BB 8
#define NVV 500
#define NOO 1500
#define DVV 512
#define DOO 32
#define HH 128
#define EPSF 1e-5f
#define WV 16
#define WO 48

// ---------------- fp32 scratch ----------------
__device__ float g_v  [BB*NVV*HH];
__device__ float g_o  [BB*NOO*HH];
__device__ float g_cvp[3*BB*NVV*HH];
__device__ float g_s1v[2*BB*NVV];
__device__ float g_s2v[2*BB*NVV];
__device__ float g_s1o[2*BB*NOO];
__device__ float g_s2o[2*BB*NOO];
__device__ unsigned g_smax[4*BB];
__device__ float g_rvsum[BB*NVV];
__device__ float g_rv  [BB*NVV];
__device__ float g_to  [BB*NOO];
__device__ unsigned g_mv[BB*NVV*WV];
__device__ unsigned g_mo[BB*NOO*WO];

// ---------------- fp16 scratch ----------------
__device__ __half h_vism[BB*NVV*DVV];
__device__ __half h_objm[BB*NOO*DOO];
__device__ __half h_aov [BB*NOO*504];
__device__ __half h_aovt[BB*NVV*1504];
__device__ __half h_oT  [BB*HH*1504];
__device__ __half h_vT  [BB*HH*504];
__device__ __half h_hvT [BB*HH*504 + 32];
__device__ __half h_hoT [BB*HH*1504 + 32];
__device__ __half h_cv  [BB*NVV*HH];
__device__ __half h_co  [BB*NOO*HH];
__device__ __half h_m1v [BB*NVV*HH];
__device__ __half h_m1o [BB*NOO*HH];
__device__ __half h_vis [BB*NVV*HH];
__device__ __half h_obj [BB*NOO*HH];
__device__ __half g_wt  [237568];

#define WT_WV1 0
#define WT_WV2 65536
#define WT_WO1 81920
#define WT_WO2 86016
#define WT_O2G1 102400
#define WT_O2G2 118784
#define WT_G2O1 135168
#define WT_G2O2 151552
#define WT_IMG 167936
#define WT_OBJ 233472

// ---------------- helpers ----------------
__device__ __forceinline__ unsigned fenc(float f) {
    unsigned u = __float_as_uint(f);
    return (u & 0x80000000u) ? ~u : (u | 0x80000000u);
}
__device__ __forceinline__ float fdec(unsigned u) {
    u = (u & 0x80000000u) ? (u & 0x7fffffffu) : ~u;
    return __uint_as_float(u);
}
__device__ __forceinline__ void mma16h(float* d, const unsigned* a, const unsigned* b) {
    asm volatile("mma.sync.aligned.m16n8k16.row.col.f32.f16.f16.f32 "
                 "{%0,%1,%2,%3},{%4,%5,%6,%7},{%8,%9},{%0,%1,%2,%3};"
                 : "+f"(d[0]), "+f"(d[1]), "+f"(d[2]), "+f"(d[3])
                 : "r"(a[0]), "r"(a[1]), "r"(a[2]), "r"(a[3]), "r"(b[0]), "r"(b[1]));
}
__device__ __forceinline__ void cpa16(unsigned dst, const void* src, int srcsz) {
    asm volatile("cp.async.cg.shared.global [%0], [%1], 16, %2;"
                 :: "r"(dst), "l"(src), "r"(srcsz));
}
__device__ __forceinline__ void cpa_commit() {
    asm volatile("cp.async.commit_group;");
}

// ---------------- fp16 GEMM: 64x128 tile, BK=32 halves, 256 threads, 4-stage ----------------
#define TBM 64
#define TBN 128
#define BKH 32
#define TSW 20
#define STAGES 4
#define AW (64*TSW)
#define BW (128*TSW)

struct GJ {
    const __half* A; const __half* Bt;
    float* Cf; __half* Ch;
    __half* CT; long ldCT; int Nrow;
    float* s1; float* s2; const float* a1; const float* a2;
    const float* bias; const float* res; const float* rowscale;
    int M, N, Ktot, Ksplit;
    int KpA, KpB;
    long sA, sB, sC;
    long spA, spB, spC;
    int nbat, nsplit, relu, gx, gy, total;
};

__device__ __forceinline__ void issue_tile_h(const GJ& j, const __half* Ab, const __half* Bb,
                                             int m0, int n0, int it, int Kact,
                                             unsigned aBase, unsigned bBase, int t)
{
    int gk0 = it * BKH;
    {
        int row = t >> 2, c = t & 3;
        int gk = gk0 + c * 8;
        int rem = Kact - gk;
        int sz = rem >= 8 ? 16 : (rem > 0 ? rem * 2 : 0);
        int gm = m0 + row;
        int s = (gm < j.M) ? sz : 0;
        const __half* src = (gm < j.M) ? &Ab[(long)gm * j.KpA + gk] : Ab;
        cpa16(aBase + (unsigned)(row * TSW + c * 4) * 4u, src, s);
    }
    {
        int row = t >> 1;
        #pragma unroll
        for (int i = 0; i < 2; i++) {
            int c = (t & 1) * 2 + i;
            int gk = gk0 + c * 8;
            int rem = Kact - gk;
            int sz = rem >= 8 ? 16 : (rem > 0 ? rem * 2 : 0);
            int gn = n0 + row;
            int s = (gn < j.N) ? sz : 0;
            const __half* src = (gn < j.N) ? &Bb[(long)gn * j.KpB + gk] : Bb;
            cpa16(bBase + (unsigned)(row * TSW + c * 4) * 4u, src, s);
        }
    }
}

__global__ void __launch_bounds__(256) gemm_h(GJ j0, GJ j1)
{
    __shared__ unsigned As[STAGES][AW];
    __shared__ unsigned Bs[STAGES][BW];

    GJ j; int bid;
    if (blockIdx.x < (unsigned)j0.total) { j = j0; bid = blockIdx.x; }
    else                                 { j = j1; bid = blockIdx.x - j0.total; }

    int per   = j.gx * j.gy;
    int bfull = bid / per;
    int rem   = bid - bfull * per;
    int by    = rem / j.gx;
    int bx    = rem - by * j.gx;
    int s     = bfull / j.nbat;
    int bb    = bfull - s * j.nbat;

    int Kact = j.Ktot - s * j.Ksplit;
    if (Kact > j.Ksplit) Kact = j.Ksplit;

    const __half* Ab = j.A  + (long)bb * j.sA + (long)s * j.spA;
    const __half* Bb = j.Bt + (long)bb * j.sB + (long)s * j.spB;
    long coff = (long)bb * j.sC + (long)s * j.spC;
    int m0 = by * TBM, n0 = bx * TBN;
    int M = j.M, N = j.N;

    int t = threadIdx.x;
    int warp = t >> 5, lane = t & 31;
    int g = lane >> 2, tg = lane & 3;
    int wm = warp >> 2, wn = warp & 3;   // 2x4 warps, warp tile 32x32

    float acc[2][4][4];
    #pragma unroll
    for (int mi = 0; mi < 2; mi++)
        #pragma unroll
        for (int ni = 0; ni < 4; ni++)
            #pragma unroll
            for (int e = 0; e < 4; e++) acc[mi][ni][e] = 0.f;

    int ntiles = (Kact + BKH - 1) / BKH;

    #pragma unroll
    for (int st = 0; st < STAGES - 1; st++) {
        if (st < ntiles) {
            unsigned aB = (unsigned)__cvta_generic_to_shared(&As[st][0]);
            unsigned bB = (unsigned)__cvta_generic_to_shared(&Bs[st][0]);
            issue_tile_h(j, Ab, Bb, m0, n0, st, Kact, aB, bB, t);
        }
        cpa_commit();
    }

    for (int it = 0; it < ntiles; it++) {
        asm volatile("cp.async.wait_group %0;" :: "n"(STAGES - 2));
        __syncthreads();

        int nx = it + STAGES - 1;
        if (nx < ntiles) {
            unsigned aB = (unsigned)__cvta_generic_to_shared(&As[nx & (STAGES - 1)][0]);
            unsigned bB = (unsigned)__cvta_generic_to_shared(&Bs[nx & (STAGES - 1)][0]);
            issue_tile_h(j, Ab, Bb, m0, n0, nx, Kact, aB, bB, t);
        }
        cpa_commit();

        const unsigned* Asb = As[it & (STAGES - 1)];
        const unsigned* Bsb = Bs[it & (STAGES - 1)];

        #pragma unroll
        for (int kg = 0; kg < 2; kg++) {
            int kw = kg * 8;
            unsigned af[2][4], bf[4][2];
            #pragma unroll
            for (int mi = 0; mi < 2; mi++) {
                int mr = wm * 32 + mi * 16 + g;
                af[mi][0] = Asb[mr * TSW + kw + tg];
                af[mi][1] = Asb[(mr + 8) * TSW + kw + tg];
                af[mi][2] = Asb[mr * TSW + kw + tg + 4];
                af[mi][3] = Asb[(mr + 8) * TSW + kw + tg + 4];
            }
            #pragma unroll
            for (int ni = 0; ni < 4; ni++) {
                int nr = wn * 32 + ni * 8 + g;
                bf[ni][0] = Bsb[nr * TSW + kw + tg];
                bf[ni][1] = Bsb[nr * TSW + kw + tg + 4];
            }
            #pragma unroll
            for (int mi = 0; mi < 2; mi++)
                #pragma unroll
                for (int ni = 0; ni < 4; ni++)
                    mma16h(acc[mi][ni], af[mi], bf[ni]);
        }
    }

    #pragma unroll
    for (int mi = 0; mi < 2; mi++) {
        #pragma unroll
        for (int hf = 0; hf < 2; hf++) {
            int row = m0 + wm * 32 + mi * 16 + g + hf * 8;
            bool rok = row < M;
            float p1 = 0.f, p2 = 0.f;
            if (rok) {
                float scale = j.rowscale ? j.rowscale[bb * M + row] : 1.f;
                #pragma unroll
                for (int ni = 0; ni < 4; ni++) {
                    int col = n0 + wn * 32 + ni * 8 + tg * 2;
                    if (col >= N) continue;
                    float v0 = acc[mi][ni][hf * 2 + 0] * scale;
                    float v1 = acc[mi][ni][hf * 2 + 1] * scale;
                    if (j.bias) { v0 += j.bias[col]; v1 += j.bias[col + 1]; }
                    long off = coff + (long)row * N + col;
                    if (j.res) { v0 += j.res[off]; v1 += j.res[off + 1]; }
                    if (j.relu) { v0 = v0 > 0.f ? v0 : 0.f; v1 = v1 > 0.f ? v1 : 0.f; }
                    if (j.Cf) *(float2*)&j.Cf[off] = make_float2(v0, v1);
                    if (j.Ch) *(__half2*)&j.Ch[off] = __floats2half2_rn(v0, v1);
                    if (j.CT) {
                        int b2 = row / j.Nrow;
                        int n2 = row - b2 * j.Nrow;
                        long tb = ((long)b2 * HH + col) * j.ldCT + n2;
                        j.CT[tb] = __float2half(v0);
                        j.CT[tb + j.ldCT] = __float2half(v1);
                    }
                    if (j.s1) {
                        p1 += v0 * j.a1[col] + v1 * j.a1[col + 1];
                        p2 += v0 * j.a2[col] + v1 * j.a2[col + 1];
                    }
                }
            }
            if (j.s1) {
                p1 += __shfl_down_sync(0xffffffffu, p1, 2);
                p1 += __shfl_down_sync(0xffffffffu, p1, 1);
                p2 += __shfl_down_sync(0xffffffffu, p2, 2);
                p2 += __shfl_down_sync(0xffffffffu, p2, 1);
                if (tg == 0 && rok) {
                    atomicAdd(&j.s1[row], p1);
                    atomicAdd(&j.s2[row], p2);
                }
            }
        }
    }
}

// ---------------- per-batch max of s2 ----------------
__global__ void smaxk(const float* s2v, const float* s2o, unsigned* smv, unsigned* smo)
{
    __shared__ float red[256];
    int bx = blockIdx.x;
    const float* s2 = (bx < BB) ? s2v : s2o;
    unsigned* sm    = (bx < BB) ? smv : smo;
    int N           = (bx < BB) ? NVV : NOO;
    int b           = (bx < BB) ? bx : bx - BB;
    float m = -1e30f;
    for (int i = threadIdx.x; i < N; i += 256) m = fmaxf(m, s2[(long)b * N + i]);
    red[threadIdx.x] = m;
    __syncthreads();
    for (int s = 128; s > 0; s >>= 1) {
        if (threadIdx.x < s) red[threadIdx.x] = fmaxf(red[threadIdx.x], red[threadIdx.x + s]);
        __syncthreads();
    }
    if (threadIdx.x == 0) sm[b] = fenc(red[0]);
}

// ---------------- adjacency -> bitmask ----------------
__global__ void maskbuild(const float* __restrict__ adjv, const float* __restrict__ adjo,
                          unsigned* __restrict__ mv, unsigned* __restrict__ mo)
{
    int warp = threadIdx.x >> 5, lane = threadIdx.x & 31;
    long gw = (long)blockIdx.x * 8 + warp;
    const float* adj; unsigned* m; int N, W; long row;
    if (gw < (long)BB * NVV) { adj = adjv; m = mv; N = NVV; W = WV; row = gw; }
    else                     { adj = adjo; m = mo; N = NOO; W = WO; row = gw - (long)BB * NVV; }
    const float* ar = adj + row * (long)N;
    unsigned* mr = m + row * (long)W;
    int nit = (W + 3) / 4;
    for (int it = 0; it < nit; it++) {
        int j0 = it * 128 + lane * 4;
        unsigned nib = 0;
        if (j0 + 3 < N) {
            float4 a = *(const float4*)&ar[j0];
            if (a.x > 0.f) nib |= 1u;
            if (a.y > 0.f) nib |= 2u;
            if (a.z > 0.f) nib |= 4u;
            if (a.w > 0.f) nib |= 8u;
        } else {
            #pragma unroll
            for (int e = 0; e < 4; e++)
                if (j0 + e < N && ar[j0 + e] > 0.f) nib |= 1u << e;
        }
        unsigned v = nib << ((lane & 7) * 4);
        v |= __shfl_xor_sync(0xffffffffu, v, 1);
        v |= __shfl_xor_sync(0xffffffffu, v, 2);
        v |= __shfl_xor_sync(0xffffffffu, v, 4);
        if ((lane & 7) == 0) {
            int w = it * 4 + (lane >> 3);
            if (w < W) mr[w] = v;
        }
    }
}

// ---------------- fp16 fused masked-softmax attention ----------------
#define AROWS 64
#define AJC 128
#define HS2 68
#define ATTN_SMEM_H ((128*HS2 + AROWS*HS2 + AROWS) * 4)

struct AJob {
    const __half* hT; const float* s1; const float* s2;
    const unsigned* smax; float* out; __half* outT; const float* tsc;
    const unsigned* mask; int W;
    long ldT; int N; int nx; int total;
};

__global__ void __launch_bounds__(256) attn_h(AJob j0, AJob j1)
{
    extern __shared__ unsigned smu[];
    unsigned* hsT = smu;
    unsigned* wsh = smu + 128 * HS2;
    float* zrow   = (float*)(wsh + AROWS * HS2);

    AJob j; int bid;
    if (blockIdx.x < (unsigned)j0.total) { j = j0; bid = blockIdx.x; }
    else                                 { j = j1; bid = blockIdx.x - j0.total; }
    int b  = bid / j.nx;
    int i0 = (bid - b * j.nx) * AROWS;
    int N  = j.N;

    int t = threadIdx.x;
    int warp = t >> 5, lane = t & 31;
    int g = lane >> 2, tg = lane & 3;
    int wm = warp >> 2, wn = warp & 3;

    const __half* hTb  = j.hT + (long)b * HH * j.ldT;
    const float* s2b   = j.s2  + (long)b * N;
    unsigned hsBase = (unsigned)__cvta_generic_to_shared(hsT);

    float acc[2][4][4];
    #pragma unroll
    for (int mi = 0; mi < 2; mi++)
        #pragma unroll
        for (int ni = 0; ni < 4; ni++)
            #pragma unroll
            for (int e = 0; e < 4; e++) acc[mi][ni][e] = 0.f;

    if (t < AROWS) zrow[t] = 0.f;

    int pr = t >> 2;
    int pj = (t & 3) * 32;
    int prow = i0 + pr;
    float s1r = 0.f, mrow = 0.f;
    if (prow < N) {
        s1r = j.s1[(long)b * N + prow];
        float x = s1r + fdec(j.smax[b]);
        mrow = x > 0.f ? x : 0.2f * x;
    }

    int sf = t >> 1;
    int ss = (t & 1) * 64;

    for (int c0 = 0; c0 < N; c0 += AJC) {
        __syncthreads();

        {
            const __half* src = hTb + (long)sf * j.ldT + c0 + ss;
            unsigned dst = hsBase + (unsigned)(sf * HS2) * 4u + (unsigned)ss * 2u;
            #pragma unroll
            for (int s = 0; s < 8; s++)
                cpa16(dst + s * 16u, src + s * 8, 16);
            cpa_commit();
        }

        float zl = 0.f;
        if (prow < N) {
            long mbase = ((long)b * N + prow) * j.W + (c0 >> 5) + (t & 3);
            int wbase = pr * HS2 + (pj >> 1);
            unsigned mw = j.mask[mbase];
            if (mw) {
                #pragma unroll
                for (int q4 = 0; q4 < 32; q4 += 4) {
                    int jj = pj + q4;
                    int gj = c0 + jj;
                    float sv[4];
                    if (gj + 3 < N) {
                        float4 s4 = *(const float4*)&s2b[gj];
                        sv[0]=s4.x; sv[1]=s4.y; sv[2]=s4.z; sv[3]=s4.w;
                    } else {
                        #pragma unroll
                        for (int e = 0; e < 4; e++)
                            sv[e] = (gj + e) < N ? s2b[gj + e] : 0.f;
                    }
                    float w[4];
                    #pragma unroll
                    for (int e = 0; e < 4; e++) {
                        w[e] = 0.f;
                        if ((mw >> (q4 + e)) & 1u) {
                            float x = s1r + sv[e];
                            float ev = x > 0.f ? x : 0.2f * x;
                            w[e] = __expf(ev - mrow);
                        }
                    }
                    __half2 u0 = __floats2half2_rn(w[0], w[1]);
                    __half2 u1 = __floats2half2_rn(w[2], w[3]);
                    *(__half2*)&wsh[wbase + (q4 >> 1)]     = u0;
                    *(__half2*)&wsh[wbase + (q4 >> 1) + 1] = u1;
                    float2 f0 = __half22float2(u0), f1 = __half22float2(u1);
                    zl += f0.x + f0.y + f1.x + f1.y;
                }
            } else {
                #pragma unroll
                for (int q = 0; q < 16; q++) wsh[wbase + q] = 0u;
            }
        } else {
            int wbase = pr * HS2 + (pj >> 1);
            #pragma unroll
            for (int q = 0; q < 16; q++) wsh[wbase + q] = 0u;
        }
        zl += __shfl_down_sync(0xffffffffu, zl, 2);
        zl += __shfl_down_sync(0xffffffffu, zl, 1);
        if ((t & 3) == 0 && prow < N) zrow[pr] += zl;

        asm volatile("cp.async.wait_group 0;");
        __syncthreads();

        #pragma unroll
        for (int kg = 0; kg < 8; kg++) {
            int kw = kg * 8;
            unsigned af[2][4], bf[4][2];
            #pragma unroll
            for (int mi = 0; mi < 2; mi++) {
                int mr = wm * 32 + mi * 16 + g;
                af[mi][0] = wsh[mr * HS2 + kw + tg];
                af[mi][1] = wsh[(mr + 8) * HS2 + kw + tg];
                af[mi][2] = wsh[mr * HS2 + kw + tg + 4];
                af[mi][3] = wsh[(mr + 8) * HS2 + kw + tg + 4];
            }
            #pragma unroll
            for (int ni = 0; ni < 4; ni++) {
                int nr = wn * 32 + ni * 8 + g;
                bf[ni][0] = hsT[nr * HS2 + kw + tg];
                bf[ni][1] = hsT[nr * HS2 + kw + tg + 4];
            }
            #pragma unroll
            for (int mi = 0; mi < 2; mi++)
                #pragma unroll
                for (int ni = 0; ni < 4; ni++)
                    mma16h(acc[mi][ni], af[mi], bf[ni]);
        }
    }
    __syncthreads();

    long tb = (long)b * HH * j.ldT;
    #pragma unroll
    for (int mi = 0; mi < 2; mi++) {
        #pragma unroll
        for (int hf = 0; hf < 2; hf++) {
            int r0 = wm * 32 + mi * 16 + g + hf * 8;
            int row = i0 + r0;
            if (row >= N) continue;
            float inv = 1.f / zrow[r0];
            float rs = j.tsc ? j.tsc[(long)b * N + row] : 1.f;
            #pragma unroll
            for (int ni = 0; ni < 4; ni++) {
                int col = wn * 32 + ni * 8 + tg * 2;
                float v0 = acc[mi][ni][hf * 2 + 0] * inv;
                float v1 = acc[mi][ni][hf * 2 + 1] * inv;
                v0 = v0 > 0.f ? v0 : 0.f;
                v1 = v1 > 0.f ? v1 : 0.f;
                long off = (long)b * N * HH + (long)row * HH + col;
                *(float2*)&j.out[off] = make_float2(v0, v1);
                j.outT[tb + (long)col * j.ldT + row]       = __float2half(v0 * rs);
                j.outT[tb + (long)(col + 1) * j.ldT + row] = __float2half(v1 * rs);
            }
        }
    }
}

// ---------------- prologue / helper kernels ----------------
__global__ void cvred(const float* __restrict__ p, const float* __restrict__ rv,
                      __half* __restrict__ cv)
{
    int i = blockIdx.x * 256 + threadIdx.x;
    if (i < BB * NVV * HH) {
        float s = p[i] + p[i + BB*NVV*HH] + p[i + 2*BB*NVV*HH];
        cv[i] = __float2half(s * rv[i >> 7]);
    }
}

__global__ void aovprep(const float* __restrict__ A, __half* __restrict__ aov,
                        __half* __restrict__ aovt, float* __restrict__ csum)
{
    __shared__ float tl[32][33];
    int b = blockIdx.z;
    int v0 = blockIdx.x * 32, o0 = blockIdx.y * 32;
    int tx = threadIdx.x & 31, ty = threadIdx.x >> 5;
    const float* Ab = A + (long)b * NOO * NVV;
    #pragma unroll
    for (int i = 0; i < 4; i++) {
        int o = o0 + ty + i * 8, v = v0 + tx;
        tl[ty + i * 8][tx] = (o < NOO && v < NVV) ? Ab[(long)o * NVV + v] : 0.f;
    }
    __syncthreads();
    #pragma unroll
    for (int i = 0; i < 4; i++) {
        int o = o0 + ty + i * 8, v = v0 + tx;
        if (o < NOO && v < 504)
            aov[(long)b * NOO * 504 + (long)o * 504 + v] = __float2half(tl[ty + i * 8][tx]);
    }
    #pragma unroll
    for (int i = 0; i < 4; i++) {
        int v = v0 + ty + i * 8, o = o0 + tx;
        if (v < NVV)
            aovt[(long)b * NVV * 1504 + (long)v * 1504 + o] = __float2half(tl[tx][ty + i * 8]);
    }
    if (ty == 0 && v0 + tx < NVV) {
        float s = 0.f;
        #pragma unroll
        for (int o = 0; o < 32; o++) s += tl[o][tx];
        atomicAdd(&csum[b * NVV + v0 + tx], s);
    }
}

__global__ void rvfin_kernel(const float* __restrict__ sums, float* __restrict__ rv, int n)
{
    int i = blockIdx.x * 256 + threadIdx.x;
    if (i < n) rv[i] = 1.f / (sums[i] + EPSF);
}

__global__ void rowsum_h(const __half* __restrict__ aov, const float* __restrict__ rv,
                         float* __restrict__ to_)
{
    int warp = threadIdx.x >> 5, lane = threadIdx.x & 31;
    int o = blockIdx.x * 8 + warp;
    int b = blockIdx.y;
    if (o >= NOO) return;
    const __half2* row = (const __half2*)(aov + (long)b * NOO * 504 + (long)o * 504);
    const float2* rvb = (const float2*)(rv + b * NVV);
    float s = 0.f;
    #pragma unroll
    for (int i = 0; i < 8; i++) {
        int idx = lane + 32 * i;
        if (idx < 250) {
            float2 f = __half22float2(row[idx]);
            float2 r = rvb[idx];
            s += f.x * r.x + f.y * r.y;
        }
    }
    #pragma unroll
    for (int off = 16; off; off >>= 1) s += __shfl_xor_sync(0xffffffffu, s, off);
    if (lane == 0) to_[b * NOO + o] = 1.f / (s + EPSF);
}

__global__ void cvtflat(const float* __restrict__ src, __half* __restrict__ dst, long n4)
{
    long i = (long)blockIdx.x * 256 + threadIdx.x;
    if (i < n4) {
        float4 v = *(const float4*)&src[i * 4];
        __half2 h0 = __floats2half2_rn(v.x, v.y);
        __half2 h1 = __floats2half2_rn(v.z, v.w);
        uint2 u;
        u.x = *(unsigned*)&h0;
        u.y = *(unsigned*)&h1;
        *(uint2*)&dst[i * 4] = u;
    }
}

struct WJobs { const float* src[10]; int K[10]; int N[10]; long off[10]; };
__global__ void wcvt(WJobs w, __half* arena)
{
    int jid = blockIdx.y;
    const float* s = w.src[jid];
    int K = w.K[jid], N = w.N[jid];
    long off = w.off[jid];
    long n = (long)K * N;
    for (long idx = (long)blockIdx.x * 256 + threadIdx.x; idx < n;
         idx += (long)gridDim.x * 256) {
        long k = idx / N;
        int c = (int)(idx - k * N);
        arena[off + (long)c * K + k] = __float2half(s[idx]);
    }
}

// ---------------- host orchestration ----------------
static GJ mkjob(const __half* A, const __half* Bt, float* Cf, __half* Ch,
                const float* bias, const float* res, const float* rowscale,
                int M, int N, int K, int KpA, int KpB,
                long sA, long sB, long sC, int relu, int nbat)
{
    GJ j;
    j.A = A; j.Bt = Bt; j.Cf = Cf; j.Ch = Ch;
    j.CT = nullptr; j.ldCT = 0; j.Nrow = 1;
    j.s1 = nullptr; j.s2 = nullptr; j.a1 = nullptr; j.a2 = nullptr;
    j.bias = bias; j.res = res; j.rowscale = rowscale;
    j.M = M; j.N = N; j.Ktot = K; j.Ksplit = K;
    j.KpA = KpA; j.KpB = KpB;
    j.sA = sA; j.sB = sB; j.sC = sC;
    j.spA = 0; j.spB = 0; j.spC = 0;
    j.nbat = nbat; j.nsplit = 1; j.relu = relu;
    j.gx = (N + TBN - 1) / TBN;
    j.gy = (M + TBM - 1) / TBM;
    j.total = j.gx * j.gy * nbat;
    return j;
}

static void launch_gemm2(const GJ& a, const GJ& b)
{
    gemm_h<<<a.total + b.total, 256>>>(a, b);
}

extern "C" void kernel_launch(void* const* d_in, const int* in_sizes, int n_in,
                              void* d_out, int out_size)
{
    const float* vis_memory = (const float*)d_in[0];
    const float* obj_memory = (const float*)d_in[1];
    const float* vis_adj    = (const float*)d_in[2];
    const float* obj_adj    = (const float*)d_in[3];
    const float* A_OV       = (const float*)d_in[4];
    const float* Wv1  = (const float*)d_in[5];
    const float* av1a = (const float*)d_in[6];
    const float* av1b = (const float*)d_in[7];
    const float* Wv2  = (const float*)d_in[8];
    const float* av2a = (const float*)d_in[9];
    const float* av2b = (const float*)d_in[10];
    const float* Wo1  = (const float*)d_in[11];
    const float* ao1a = (const float*)d_in[12];
    const float* ao1b = (const float*)d_in[13];
    const float* Wo2  = (const float*)d_in[14];
    const float* ao2a = (const float*)d_in[15];
    const float* ao2b = (const float*)d_in[16];
    const float* g2o_W1 = (const float*)d_in[17];
    const float* g2o_b1 = (const float*)d_in[18];
    const float* g2o_W2 = (const float*)d_in[19];
    const float* g2o_b2 = (const float*)d_in[20];
    const float* o2g_W1 = (const float*)d_in[21];
    const float* o2g_b1 = (const float*)d_in[22];
    const float* o2g_W2 = (const float*)d_in[23];
    const float* o2g_b2 = (const float*)d_in[24];
    const float* img_W = (const float*)d_in[25];
    const float* img_b = (const float*)d_in[26];
    const float* obj_W = (const float*)d_in[27];
    const float* obj_b = (const float*)d_in[28];

    float *p_v, *p_o, *p_cvp, *p_s1v, *p_s2v, *p_s1o, *p_s2o;
    float *p_rvsum, *p_rv, *p_to;
    unsigned *p_smax, *p_mv, *p_mo;
    __half *ph_vism, *ph_objm, *ph_aov, *ph_aovt, *ph_oT, *ph_vT, *ph_hvT, *ph_hoT;
    __half *ph_cv, *ph_co, *ph_m1v, *ph_m1o, *ph_vis, *ph_obj, *ph_wt;

    cudaGetSymbolAddress((void**)&p_v,   g_v);
    cudaGetSymbolAddress((void**)&p_o,   g_o);
    cudaGetSymbolAddress((void**)&p_cvp, g_cvp);
    cudaGetSymbolAddress((void**)&p_s1v, g_s1v);
    cudaGetSymbolAddress((void**)&p_s2v, g_s2v);
    cudaGetSymbolAddress((void**)&p_s1o, g_s1o);
    cudaGetSymbolAddress((void**)&p_s2o, g_s2o);
    cudaGetSymbolAddress((void**)&p_smax, g_smax);
    cudaGetSymbolAddress((void**)&p_rvsum, g_rvsum);
    cudaGetSymbolAddress((void**)&p_rv,  g_rv);
    cudaGetSymbolAddress((void**)&p_to,  g_to);
    cudaGetSymbolAddress((void**)&p_mv,  g_mv);
    cudaGetSymbolAddress((void**)&p_mo,  g_mo);
    cudaGetSymbolAddress((void**)&ph_vism, h_vism);
    cudaGetSymbolAddress((void**)&ph_objm, h_objm);
    cudaGetSymbolAddress((void**)&ph_aov,  h_aov);
    cudaGetSymbolAddress((void**)&ph_aovt, h_aovt);
    cudaGetSymbolAddress((void**)&ph_oT,   h_oT);
    cudaGetSymbolAddress((void**)&ph_vT,   h_vT);
    cudaGetSymbolAddress((void**)&ph_hvT,  h_hvT);
    cudaGetSymbolAddress((void**)&ph_hoT,  h_hoT);
    cudaGetSymbolAddress((void**)&ph_cv,   h_cv);
    cudaGetSymbolAddress((void**)&ph_co,   h_co);
    cudaGetSymbolAddress((void**)&ph_m1v,  h_m1v);
    cudaGetSymbolAddress((void**)&ph_m1o,  h_m1o);
    cudaGetSymbolAddress((void**)&ph_vis,  h_vis);
    cudaGetSymbolAddress((void**)&ph_obj,  h_obj);
    cudaGetSymbolAddress((void**)&ph_wt,   g_wt);

    cudaFuncSetAttribute(attn_h, cudaFuncAttributeMaxDynamicSharedMemorySize, ATTN_SMEM_H);

    // ---- prologue ----
    cudaMemsetAsync(p_rvsum, 0, BB * NVV * sizeof(float));
    cudaMemsetAsync(p_s1v, 0, 2 * BB * NVV * sizeof(float));
    cudaMemsetAsync(p_s2v, 0, 2 * BB * NVV * sizeof(float));
    cudaMemsetAsync(p_s1o, 0, 2 * BB * NOO * sizeof(float));
    cudaMemsetAsync(p_s2o, 0, 2 * BB * NOO * sizeof(float));
    maskbuild<<<(BB * (NVV + NOO) + 7) / 8, 256>>>(vis_adj, obj_adj, p_mv, p_mo);
    aovprep<<<dim3(16, 47, BB), 256>>>(A_OV, ph_aov, ph_aovt, p_rvsum);
    rvfin_kernel<<<(BB * NVV + 255) / 256, 256>>>(p_rvsum, p_rv, BB * NVV);
    rowsum_h<<<dim3((NOO + 7) / 8, BB), 256>>>(ph_aov, p_rv, p_to);
    cvtflat<<<(BB * NVV * DVV / 4 + 255) / 256, 256>>>(vis_memory, ph_vism, (long)BB * NVV * DVV / 4);
    cvtflat<<<(BB * NOO * DOO / 4 + 255) / 256, 256>>>(obj_memory, ph_objm, (long)BB * NOO * DOO / 4);
    {
        WJobs w;
        const float* srcs[10] = { Wv1, Wv2, Wo1, Wo2, o2g_W1, o2g_W2, g2o_W1, g2o_W2, img_W, obj_W };
        int Ks[10] = { 512, 128, 32, 128, 128, 128, 128, 128, 128, 128 };
        int Ns[10] = { 128, 128, 128, 128, 128, 128, 128, 128, 512, 32 };
        long offs[10] = { WT_WV1, WT_WV2, WT_WO1, WT_WO2, WT_O2G1, WT_O2G2,
                          WT_G2O1, WT_G2O2, WT_IMG, WT_OBJ };
        for (int i = 0; i < 10; i++) { w.src[i] = srcs[i]; w.K[i] = Ks[i]; w.N[i] = Ns[i]; w.off[i] = offs[i]; }
        wcvt<<<dim3(64, 10), 256>>>(w, ph_wt);
    }

    for (int round = 0; round < 2; round++) {
        const __half* xv = (round == 0) ? ph_vism : ph_vis;
        const __half* xo = (round == 0) ? ph_objm : ph_obj;
        int Kv = (round == 0) ? DVV : HH;
        int Ko = (round == 0) ? DOO : HH;
        const __half* Wvt = ph_wt + ((round == 0) ? WT_WV1 : WT_WV2);
        const __half* Wot = ph_wt + ((round == 0) ? WT_WO1 : WT_WO2);
        const float* ava = (round == 0) ? av1a : av2a;
        const float* avb = (round == 0) ? av1b : av2b;
        const float* aoa = (round == 0) ? ao1a : ao2a;
        const float* aob = (round == 0) ? ao1b : ao2b;
        unsigned* smv = p_smax + (round * 2 + 0) * BB;
        unsigned* smo = p_smax + (round * 2 + 1) * BB;
        float* s1v = p_s1v + round * BB * NVV;
        float* s2v = p_s2v + round * BB * NVV;
        float* s1o = p_s1o + round * BB * NOO;
        float* s2o = p_s2o + round * BB * NOO;

        // h = x @ W  (transposed fp16 out + fused scores)
        {
            GJ jv = mkjob(xv, Wvt, nullptr, nullptr, nullptr, nullptr, nullptr,
                          BB * NVV, HH, Kv, Kv, Kv, 0, 0, 0, 0, 1);
            jv.CT = ph_hvT; jv.ldCT = 504; jv.Nrow = NVV;
            jv.s1 = s1v; jv.s2 = s2v; jv.a1 = ava; jv.a2 = avb;
            GJ jo = mkjob(xo, Wot, nullptr, nullptr, nullptr, nullptr, nullptr,
                          BB * NOO, HH, Ko, Ko, Ko, 0, 0, 0, 0, 1);
            jo.CT = ph_hoT; jo.ldCT = 1504; jo.Nrow = NOO;
            jo.s1 = s1o; jo.s2 = s2o; jo.a1 = aoa; jo.a2 = aob;
            launch_gemm2(jv, jo);
        }

        // per-batch max of s2
        smaxk<<<2 * BB, 256>>>(s2v, s2o, smv, smo);

        // attention (fp16 mma, mask-based)
        {
            int nxv = (NVV + AROWS - 1) / AROWS;
            int nxo = (NOO + AROWS - 1) / AROWS;
            AJob av_ = { ph_hvT, s1v, s2v, smv, p_v, ph_vT, p_rv,
                         p_mv, WV, 504, NVV, nxv, nxv * BB };
            AJob ao_ = { ph_hoT, s1o, s2o, smo, p_o, ph_oT, nullptr,
                         p_mo, WO, 1504, NOO, nxo, nxo * BB };
            attn_h<<<av_.total + ao_.total, 256, ATTN_SMEM_H>>>(av_, ao_);
        }

        // cv partials (split-K x3 @512) || co = to ⊙ (A_OV @ (rv⊙v))
        {
            GJ jcv = mkjob(ph_aovt, ph_oT, p_cvp, nullptr, nullptr, nullptr, nullptr,
                           NVV, HH, NOO, 1504, 1504,
                           (long)NVV * 1504, (long)HH * 1504, (long)NVV * HH, 0, BB);
            jcv.Ksplit = 512; jcv.nsplit = 3;
            jcv.spA = 512; jcv.spB = 512; jcv.spC = (long)BB * NVV * HH;
            jcv.total = jcv.gx * jcv.gy * BB * 3;
            GJ jco = mkjob(ph_aov, ph_vT, nullptr, ph_co, nullptr, nullptr, p_to,
                           NOO, HH, NVV, 504, 504,
                           (long)NOO * 504, (long)HH * 504, (long)NOO * HH, 0, BB);
            launch_gemm2(jcv, jco);
        }
        cvred<<<(BB * NVV * HH + 255) / 256, 256>>>(p_cvp, p_rv, ph_cv);

        // mlp layer 1 (relu)
        launch_gemm2(
            mkjob(ph_cv, ph_wt + WT_O2G1, nullptr, ph_m1v, o2g_b1, nullptr, nullptr,
                  BB * NVV, HH, HH, HH, HH, 0, 0, 0, 1, 1),
            mkjob(ph_co, ph_wt + WT_G2O1, nullptr, ph_m1o, g2o_b1, nullptr, nullptr,
                  BB * NOO, HH, HH, HH, HH, 0, 0, 0, 1, 1));

        // mlp layer 2 + residual
        launch_gemm2(
            mkjob(ph_m1v, ph_wt + WT_O2G2, nullptr, ph_vis, o2g_b2, p_v, nullptr,
                  BB * NVV, HH, HH, HH, HH, 0, 0, 0, 0, 1),
            mkjob(ph_m1o, ph_wt + WT_G2O2, nullptr, ph_obj, g2o_b2, p_o, nullptr,
                  BB * NOO, HH, HH, HH, HH, 0, 0, 0, 0, 1));
    }

    // output projections
    float* out_vis = (float*)d_out;
    float* out_obj = out_vis + (long)BB * NVV * DVV;
    launch_gemm2(
        mkjob(ph_vis, ph_wt + WT_IMG, out_vis, nullptr, img_b, nullptr, nullptr,
              BB * NVV, DVV, HH, HH, HH, 0, 0, 0, 0, 1),
        mkjob(ph_obj, ph_wt + WT_OBJ, out_obj, nullptr, obj_b, nullptr, nullptr,
              BB * NOO, DOO, HH, HH, HH, 0, 0, 0, 0, 1));
}

// round 14
// speedup vs baseline: 1.0826x; 1.0826x over previous
#include <cuda_runtime.h>
#include <cuda_fp16.h>
#include <math.h>

#define BB 8
#define NVV 500
#define NOO 1500
#define DVV 512
#define DOO 32
#define HH 128
#define EPSF 1e-5f
#define WV 16
#define WO 48

// ---------------- fp32 scratch ----------------
__device__ float g_v  [BB*NVV*HH];
__device__ float g_o  [BB*NOO*HH];
__device__ float g_cvp[3*BB*NVV*HH];
__device__ float g_zbuf[68000];       // [rvsum 4000][s1v 8000][s2v 8000][s1o 24000][s2o 24000]
__device__ unsigned g_smax[4*BB];
__device__ float g_rv  [BB*NVV];
__device__ float g_to  [BB*NOO];
__device__ unsigned g_mv[BB*NVV*WV];
__device__ unsigned g_mo[BB*NOO*WO];

// ---------------- fp16 scratch ----------------
__device__ __half h_vism[BB*NVV*DVV];
__device__ __half h_objm[BB*NOO*DOO];
__device__ __half h_aov [BB*NOO*504];
__device__ __half h_aovt[BB*NVV*1504];
__device__ __half h_oT  [BB*HH*1504];
__device__ __half h_vT  [BB*HH*504];
__device__ __half h_hvT [BB*HH*504 + 32];
__device__ __half h_hoT [BB*HH*1504 + 32];
__device__ __half h_cv  [BB*NVV*HH];
__device__ __half h_co  [BB*NOO*HH];
__device__ __half h_m1v [BB*NVV*HH];
__device__ __half h_m1o [BB*NOO*HH];
__device__ __half h_vis [BB*NVV*HH];
__device__ __half h_obj [BB*NOO*HH];
__device__ __half g_wt  [237568];

#define WT_WV1 0
#define WT_WV2 65536
#define WT_WO1 81920
#define WT_WO2 86016
#define WT_O2G1 102400
#define WT_O2G2 118784
#define WT_G2O1 135168
#define WT_G2O2 151552
#define WT_IMG 167936
#define WT_OBJ 233472

// ---------------- helpers ----------------
__device__ __forceinline__ unsigned fenc(float f) {
    unsigned u = __float_as_uint(f);
    return (u & 0x80000000u) ? ~u : (u | 0x80000000u);
}
__device__ __forceinline__ float fdec(unsigned u) {
    u = (u & 0x80000000u) ? (u & 0x7fffffffu) : ~u;
    return __uint_as_float(u);
}
__device__ __forceinline__ void mma16h(float* d, const unsigned* a, const unsigned* b) {
    asm volatile("mma.sync.aligned.m16n8k16.row.col.f32.f16.f16.f32 "
                 "{%0,%1,%2,%3},{%4,%5,%6,%7},{%8,%9},{%0,%1,%2,%3};"
                 : "+f"(d[0]), "+f"(d[1]), "+f"(d[2]), "+f"(d[3])
                 : "r"(a[0]), "r"(a[1]), "r"(a[2]), "r"(a[3]), "r"(b[0]), "r"(b[1]));
}
__device__ __forceinline__ void cpa16(unsigned dst, const void* src, int srcsz) {
    asm volatile("cp.async.cg.shared.global [%0], [%1], 16, %2;"
                 :: "r"(dst), "l"(src), "r"(srcsz));
}
__device__ __forceinline__ void cpa_commit() {
    asm volatile("cp.async.commit_group;");
}

// ---------------- fp16 GEMM: 64x64 tile, BK=32 halves, 256 threads, 4-stage ----------------
#define TBM 64
#define TBN 64
#define BKH 32
#define TSW 20
#define STAGES 4
#define TILEW (64*TSW)

struct GJ {
    const __half* A; const __half* Bt;
    float* Cf; __half* Ch;
    __half* CT; long ldCT; int Nrow;
    float* s1; float* s2; const float* a1; const float* a2;
    const float* bias; const float* res; const float* rowscale;
    int M, N, Ktot, Ksplit;
    int KpA, KpB;
    long sA, sB, sC;
    long spA, spB, spC;
    int nbat, nsplit, relu, gx, gy, total;
};

__device__ __forceinline__ void issue_tile_h(const GJ& j, const __half* Ab, const __half* Bb,
                                             int m0, int n0, int it, int Kact,
                                             unsigned aBase, unsigned bBase, int t)
{
    int row = t >> 2, c = t & 3;
    int gk = it * BKH + c * 8;
    int rem = Kact - gk;
    int sz = rem >= 8 ? 16 : (rem > 0 ? rem * 2 : 0);
    unsigned dstoff = (unsigned)(row * TSW + c * 4) * 4u;
    {
        int gm = m0 + row;
        int s = (gm < j.M) ? sz : 0;
        const __half* src = (gm < j.M) ? &Ab[(long)gm * j.KpA + gk] : Ab;
        cpa16(aBase + dstoff, src, s);
    }
    {
        int gn = n0 + row;
        int s = (gn < j.N) ? sz : 0;
        const __half* src = (gn < j.N) ? &Bb[(long)gn * j.KpB + gk] : Bb;
        cpa16(bBase + dstoff, src, s);
    }
}

__global__ void __launch_bounds__(256) gemm_h(GJ j0, GJ j1)
{
    __shared__ unsigned As[STAGES][TILEW];
    __shared__ unsigned Bs[STAGES][TILEW];

    GJ j; int bid;
    if (blockIdx.x < (unsigned)j0.total) { j = j0; bid = blockIdx.x; }
    else                                 { j = j1; bid = blockIdx.x - j0.total; }

    int per   = j.gx * j.gy;
    int bfull = bid / per;
    int rem   = bid - bfull * per;
    int by    = rem / j.gx;
    int bx    = rem - by * j.gx;
    int s     = bfull / j.nbat;
    int bb    = bfull - s * j.nbat;

    int Kact = j.Ktot - s * j.Ksplit;
    if (Kact > j.Ksplit) Kact = j.Ksplit;

    const __half* Ab = j.A  + (long)bb * j.sA + (long)s * j.spA;
    const __half* Bb = j.Bt + (long)bb * j.sB + (long)s * j.spB;
    long coff = (long)bb * j.sC + (long)s * j.spC;
    int m0 = by * TBM, n0 = bx * TBN;
    int M = j.M, N = j.N;

    int t = threadIdx.x;
    int warp = t >> 5, lane = t & 31;
    int g = lane >> 2, tg = lane & 3;
    int wm = warp >> 1, wn = warp & 1;

    float acc[4][4];
    #pragma unroll
    for (int ni = 0; ni < 4; ni++)
        #pragma unroll
        for (int e = 0; e < 4; e++) acc[ni][e] = 0.f;

    int ntiles = (Kact + BKH - 1) / BKH;

    #pragma unroll
    for (int st = 0; st < STAGES - 1; st++) {
        if (st < ntiles) {
            unsigned aB = (unsigned)__cvta_generic_to_shared(&As[st][0]);
            unsigned bB = (unsigned)__cvta_generic_to_shared(&Bs[st][0]);
            issue_tile_h(j, Ab, Bb, m0, n0, st, Kact, aB, bB, t);
        }
        cpa_commit();
    }

    for (int it = 0; it < ntiles; it++) {
        asm volatile("cp.async.wait_group %0;" :: "n"(STAGES - 2));
        __syncthreads();

        int nx = it + STAGES - 1;
        if (nx < ntiles) {
            unsigned aB = (unsigned)__cvta_generic_to_shared(&As[nx & (STAGES - 1)][0]);
            unsigned bB = (unsigned)__cvta_generic_to_shared(&Bs[nx & (STAGES - 1)][0]);
            issue_tile_h(j, Ab, Bb, m0, n0, nx, Kact, aB, bB, t);
        }
        cpa_commit();

        const unsigned* Asb = As[it & (STAGES - 1)];
        const unsigned* Bsb = Bs[it & (STAGES - 1)];

        #pragma unroll
        for (int kg = 0; kg < 2; kg++) {
            int kw = kg * 8;
            unsigned af[4], bf[4][2];
            int mb = wm * 16 + g;
            af[0] = Asb[mb * TSW + kw + tg];
            af[1] = Asb[(mb + 8) * TSW + kw + tg];
            af[2] = Asb[mb * TSW + kw + tg + 4];
            af[3] = Asb[(mb + 8) * TSW + kw + tg + 4];
            #pragma unroll
            for (int ni = 0; ni < 4; ni++) {
                int nb = wn * 32 + ni * 8 + g;
                bf[ni][0] = Bsb[nb * TSW + kw + tg];
                bf[ni][1] = Bsb[nb * TSW + kw + tg + 4];
            }
            #pragma unroll
            for (int ni = 0; ni < 4; ni++)
                mma16h(acc[ni], af, bf[ni]);
        }
    }

    #pragma unroll
    for (int hf = 0; hf < 2; hf++) {
        int row = m0 + wm * 16 + g + hf * 8;
        bool rok = row < M;
        float p1 = 0.f, p2 = 0.f;
        if (rok) {
            float scale = j.rowscale ? j.rowscale[bb * M + row] : 1.f;
            #pragma unroll
            for (int ni = 0; ni < 4; ni++) {
                int col = n0 + wn * 32 + ni * 8 + tg * 2;
                if (col >= N) continue;
                float v0 = acc[ni][hf * 2 + 0] * scale;
                float v1 = acc[ni][hf * 2 + 1] * scale;
                if (j.bias) { v0 += j.bias[col]; v1 += j.bias[col + 1]; }
                long off = coff + (long)row * N + col;
                if (j.res) { v0 += j.res[off]; v1 += j.res[off + 1]; }
                if (j.relu) { v0 = v0 > 0.f ? v0 : 0.f; v1 = v1 > 0.f ? v1 : 0.f; }
                if (j.Cf) *(float2*)&j.Cf[off] = make_float2(v0, v1);
                if (j.Ch) *(__half2*)&j.Ch[off] = __floats2half2_rn(v0, v1);
                if (j.CT) {
                    int b2 = row / j.Nrow;
                    int n2 = row - b2 * j.Nrow;
                    long tb = ((long)b2 * HH + col) * j.ldCT + n2;
                    j.CT[tb] = __float2half(v0);
                    j.CT[tb + j.ldCT] = __float2half(v1);
                }
                if (j.s1) {
                    p1 += v0 * j.a1[col] + v1 * j.a1[col + 1];
                    p2 += v0 * j.a2[col] + v1 * j.a2[col + 1];
                }
            }
        }
        if (j.s1) {
            p1 += __shfl_down_sync(0xffffffffu, p1, 2);
            p1 += __shfl_down_sync(0xffffffffu, p1, 1);
            p2 += __shfl_down_sync(0xffffffffu, p2, 2);
            p2 += __shfl_down_sync(0xffffffffu, p2, 1);
            if (tg == 0 && rok) {
                atomicAdd(&j.s1[row], p1);
                atomicAdd(&j.s2[row], p2);
            }
        }
    }
}

// ---------------- per-batch max of s2 ----------------
__global__ void smaxk(const float* s2v, const float* s2o, unsigned* smv, unsigned* smo)
{
    __shared__ float red[256];
    int bx = blockIdx.x;
    const float* s2 = (bx < BB) ? s2v : s2o;
    unsigned* sm    = (bx < BB) ? smv : smo;
    int N           = (bx < BB) ? NVV : NOO;
    int b           = (bx < BB) ? bx : bx - BB;
    float m = -1e30f;
    for (int i = threadIdx.x; i < N; i += 256) m = fmaxf(m, s2[(long)b * N + i]);
    red[threadIdx.x] = m;
    __syncthreads();
    for (int s = 128; s > 0; s >>= 1) {
        if (threadIdx.x < s) red[threadIdx.x] = fmaxf(red[threadIdx.x], red[threadIdx.x + s]);
        __syncthreads();
    }
    if (threadIdx.x == 0) sm[b] = fenc(red[0]);
}

// ---------------- merged prologue: maskbuild | aovprep | cvtflat x2 | wcvt ----------------
#define NB_MASK 2000
#define NB_AOV  (16*47*BB)
#define NB_CVV  2000
#define NB_CVO  375
#define NB_W    640
#define NB_PREP (NB_MASK + NB_AOV + NB_CVV + NB_CVO + NB_W)

struct WJobs { const float* src[10]; int K[10]; int N[10]; long off[10]; };

__global__ void __launch_bounds__(256) prep(
    const float* __restrict__ adjv, const float* __restrict__ adjo,
    unsigned* __restrict__ mv, unsigned* __restrict__ mo,
    const float* __restrict__ Aov, __half* __restrict__ aov,
    __half* __restrict__ aovt, float* __restrict__ csum,
    const float* __restrict__ vism, __half* __restrict__ vismh,
    const float* __restrict__ objm, __half* __restrict__ objmh,
    WJobs w, __half* __restrict__ arena)
{
    __shared__ float tl[32][33];
    int bidx = blockIdx.x;
    int tid = threadIdx.x;

    if (bidx < NB_MASK) {
        // ---- maskbuild ----
        int warp = tid >> 5, lane = tid & 31;
        long gw = (long)bidx * 8 + warp;
        const float* adj; unsigned* m; int N, W; long row;
        if (gw < (long)BB * NVV) { adj = adjv; m = mv; N = NVV; W = WV; row = gw; }
        else                     { adj = adjo; m = mo; N = NOO; W = WO; row = gw - (long)BB * NVV; }
        const float* ar = adj + row * (long)N;
        unsigned* mr = m + row * (long)W;
        int nit = (W + 3) / 4;
        for (int it = 0; it < nit; it++) {
            int j0 = it * 128 + lane * 4;
            unsigned nib = 0;
            if (j0 + 3 < N) {
                float4 a = *(const float4*)&ar[j0];
                if (a.x > 0.f) nib |= 1u;
                if (a.y > 0.f) nib |= 2u;
                if (a.z > 0.f) nib |= 4u;
                if (a.w > 0.f) nib |= 8u;
            } else {
                #pragma unroll
                for (int e = 0; e < 4; e++)
                    if (j0 + e < N && ar[j0 + e] > 0.f) nib |= 1u << e;
            }
            unsigned v = nib << ((lane & 7) * 4);
            v |= __shfl_xor_sync(0xffffffffu, v, 1);
            v |= __shfl_xor_sync(0xffffffffu, v, 2);
            v |= __shfl_xor_sync(0xffffffffu, v, 4);
            if ((lane & 7) == 0) {
                int ww = it * 4 + (lane >> 3);
                if (ww < W) mr[ww] = v;
            }
        }
        return;
    }
    bidx -= NB_MASK;
    if (bidx < NB_AOV) {
        // ---- aovprep ----
        int b = bidx / (16 * 47);
        int r2 = bidx - b * (16 * 47);
        int yb = r2 / 16;
        int xb = r2 - yb * 16;
        int v0 = xb * 32, o0 = yb * 32;
        int tx = tid & 31, ty = tid >> 5;
        const float* Ab = Aov + (long)b * NOO * NVV;
        #pragma unroll
        for (int i = 0; i < 4; i++) {
            int o = o0 + ty + i * 8, v = v0 + tx;
            tl[ty + i * 8][tx] = (o < NOO && v < NVV) ? Ab[(long)o * NVV + v] : 0.f;
        }
        __syncthreads();
        #pragma unroll
        for (int i = 0; i < 4; i++) {
            int o = o0 + ty + i * 8, v = v0 + tx;
            if (o < NOO && v < 504)
                aov[(long)b * NOO * 504 + (long)o * 504 + v] = __float2half(tl[ty + i * 8][tx]);
        }
        #pragma unroll
        for (int i = 0; i < 4; i++) {
            int v = v0 + ty + i * 8, o = o0 + tx;
            if (v < NVV)
                aovt[(long)b * NVV * 1504 + (long)v * 1504 + o] = __float2half(tl[tx][ty + i * 8]);
        }
        if (ty == 0 && v0 + tx < NVV) {
            float s = 0.f;
            #pragma unroll
            for (int o = 0; o < 32; o++) s += tl[o][tx];
            atomicAdd(&csum[b * NVV + v0 + tx], s);
        }
        return;
    }
    bidx -= NB_AOV;
    if (bidx < NB_CVV + NB_CVO) {
        // ---- cvtflat (vis then obj) ----
        const float* src; __half* dst; long n4; long i0;
        if (bidx < NB_CVV) { src = vism; dst = vismh; n4 = (long)BB * NVV * DVV / 4; i0 = (long)bidx * 256; }
        else { src = objm; dst = objmh; n4 = (long)BB * NOO * DOO / 4; i0 = (long)(bidx - NB_CVV) * 256; }
        long i = i0 + tid;
        if (i < n4) {
            float4 v = *(const float4*)&src[i * 4];
            __half2 h0 = __floats2half2_rn(v.x, v.y);
            __half2 h1 = __floats2half2_rn(v.z, v.w);
            uint2 u;
            u.x = *(unsigned*)&h0;
            u.y = *(unsigned*)&h1;
            *(uint2*)&dst[i * 4] = u;
        }
        return;
    }
    bidx -= NB_CVV + NB_CVO;
    {
        // ---- wcvt ----
        int jid = bidx / 64;
        int xb = bidx - jid * 64;
        const float* s = w.src[jid];
        int K = w.K[jid], N = w.N[jid];
        long off = w.off[jid];
        long n = (long)K * N;
        for (long idx = (long)xb * 256 + tid; idx < n; idx += 64L * 256) {
            long k = idx / N;
            int c = (int)(idx - k * N);
            arena[off + (long)c * K + k] = __float2half(s[idx]);
        }
    }
}

// ---------------- fp16 fused masked-softmax attention ----------------
#define AROWS 64
#define AJC 128
#define HS2 68
#define ATTN_SMEM_H ((128*HS2 + AROWS*HS2 + AROWS) * 4)

struct AJob {
    const __half* hT; const float* s1; const float* s2;
    const unsigned* smax; float* out; __half* outT; const float* tsc;
    const unsigned* mask; int W;
    long ldT; int N; int nx; int total;
};

__global__ void __launch_bounds__(256) attn_h(AJob j0, AJob j1)
{
    extern __shared__ unsigned smu[];
    unsigned* hsT = smu;
    unsigned* wsh = smu + 128 * HS2;
    float* zrow   = (float*)(wsh + AROWS * HS2);

    AJob j; int bid;
    if (blockIdx.x < (unsigned)j0.total) { j = j0; bid = blockIdx.x; }
    else                                 { j = j1; bid = blockIdx.x - j0.total; }
    int b  = bid / j.nx;
    int i0 = (bid - b * j.nx) * AROWS;
    int N  = j.N;

    int t = threadIdx.x;
    int warp = t >> 5, lane = t & 31;
    int g = lane >> 2, tg = lane & 3;
    int wm = warp >> 2, wn = warp & 3;

    const __half* hTb  = j.hT + (long)b * HH * j.ldT;
    const float* s2b   = j.s2  + (long)b * N;
    unsigned hsBase = (unsigned)__cvta_generic_to_shared(hsT);

    float acc[2][4][4];
    #pragma unroll
    for (int mi = 0; mi < 2; mi++)
        #pragma unroll
        for (int ni = 0; ni < 4; ni++)
            #pragma unroll
            for (int e = 0; e < 4; e++) acc[mi][ni][e] = 0.f;

    if (t < AROWS) zrow[t] = 0.f;

    int pr = t >> 2;
    int pj = (t & 3) * 32;
    int prow = i0 + pr;
    float s1r = 0.f, mrow = 0.f;
    if (prow < N) {
        s1r = j.s1[(long)b * N + prow];
        float x = s1r + fdec(j.smax[b]);
        mrow = x > 0.f ? x : 0.2f * x;
    }

    int sf = t >> 1;
    int ss = (t & 1) * 64;

    for (int c0 = 0; c0 < N; c0 += AJC) {
        __syncthreads();

        {
            const __half* src = hTb + (long)sf * j.ldT + c0 + ss;
            unsigned dst = hsBase + (unsigned)(sf * HS2) * 4u + (unsigned)ss * 2u;
            #pragma unroll
            for (int s = 0; s < 8; s++)
                cpa16(dst + s * 16u, src + s * 8, 16);
            cpa_commit();
        }

        float zl = 0.f;
        if (prow < N) {
            long mbase = ((long)b * N + prow) * j.W + (c0 >> 5) + (t & 3);
            int wbase = pr * HS2 + (pj >> 1);
            unsigned mw = j.mask[mbase];
            if (mw) {
                #pragma unroll
                for (int q4 = 0; q4 < 32; q4 += 4) {
                    int jj = pj + q4;
                    int gj = c0 + jj;
                    float sv[4];
                    if (gj + 3 < N) {
                        float4 s4 = *(const float4*)&s2b[gj];
                        sv[0]=s4.x; sv[1]=s4.y; sv[2]=s4.z; sv[3]=s4.w;
                    } else {
                        #pragma unroll
                        for (int e = 0; e < 4; e++)
                            sv[e] = (gj + e) < N ? s2b[gj + e] : 0.f;
                    }
                    float w[4];
                    #pragma unroll
                    for (int e = 0; e < 4; e++) {
                        w[e] = 0.f;
                        if ((mw >> (q4 + e)) & 1u) {
                            float x = s1r + sv[e];
                            float ev = x > 0.f ? x : 0.2f * x;
                            w[e] = __expf(ev - mrow);
                        }
                    }
                    __half2 u0 = __floats2half2_rn(w[0], w[1]);
                    __half2 u1 = __floats2half2_rn(w[2], w[3]);
                    *(__half2*)&wsh[wbase + (q4 >> 1)]     = u0;
                    *(__half2*)&wsh[wbase + (q4 >> 1) + 1] = u1;
                    float2 f0 = __half22float2(u0), f1 = __half22float2(u1);
                    zl += f0.x + f0.y + f1.x + f1.y;
                }
            } else {
                #pragma unroll
                for (int q = 0; q < 16; q++) wsh[wbase + q] = 0u;
            }
        } else {
            int wbase = pr * HS2 + (pj >> 1);
            #pragma unroll
            for (int q = 0; q < 16; q++) wsh[wbase + q] = 0u;
        }
        zl += __shfl_down_sync(0xffffffffu, zl, 2);
        zl += __shfl_down_sync(0xffffffffu, zl, 1);
        if ((t & 3) == 0 && prow < N) zrow[pr] += zl;

        asm volatile("cp.async.wait_group 0;");
        __syncthreads();

        #pragma unroll
        for (int kg = 0; kg < 8; kg++) {
            int kw = kg * 8;
            unsigned af[2][4], bf[4][2];
            #pragma unroll
            for (int mi = 0; mi < 2; mi++) {
                int mr = wm * 32 + mi * 16 + g;
                af[mi][0] = wsh[mr * HS2 + kw + tg];
                af[mi][1] = wsh[(mr + 8) * HS2 + kw + tg];
                af[mi][2] = wsh[mr * HS2 + kw + tg + 4];
                af[mi][3] = wsh[(mr + 8) * HS2 + kw + tg + 4];
            }
            #pragma unroll
            for (int ni = 0; ni < 4; ni++) {
                int nr = wn * 32 + ni * 8 + g;
                bf[ni][0] = hsT[nr * HS2 + kw + tg];
                bf[ni][1] = hsT[nr * HS2 + kw + tg + 4];
            }
            #pragma unroll
            for (int mi = 0; mi < 2; mi++)
                #pragma unroll
                for (int ni = 0; ni < 4; ni++)
                    mma16h(acc[mi][ni], af[mi], bf[ni]);
        }
    }
    __syncthreads();

    long tb = (long)b * HH * j.ldT;
    #pragma unroll
    for (int mi = 0; mi < 2; mi++) {
        #pragma unroll
        for (int hf = 0; hf < 2; hf++) {
            int r0 = wm * 32 + mi * 16 + g + hf * 8;
            int row = i0 + r0;
            if (row >= N) continue;
            float inv = 1.f / zrow[r0];
            float rs = j.tsc ? j.tsc[(long)b * N + row] : 1.f;
            #pragma unroll
            for (int ni = 0; ni < 4; ni++) {
                int col = wn * 32 + ni * 8 + tg * 2;
                float v0 = acc[mi][ni][hf * 2 + 0] * inv;
                float v1 = acc[mi][ni][hf * 2 + 1] * inv;
                v0 = v0 > 0.f ? v0 : 0.f;
                v1 = v1 > 0.f ? v1 : 0.f;
                long off = (long)b * N * HH + (long)row * HH + col;
                *(float2*)&j.out[off] = make_float2(v0, v1);
                j.outT[tb + (long)col * j.ldT + row]       = __float2half(v0 * rs);
                j.outT[tb + (long)(col + 1) * j.ldT + row] = __float2half(v1 * rs);
            }
        }
    }
}

// ---------------- remaining helpers ----------------
__global__ void cvred(const float* __restrict__ p, const float* __restrict__ rv,
                      __half* __restrict__ cv)
{
    int i = blockIdx.x * 256 + threadIdx.x;
    if (i < BB * NVV * HH) {
        float s = p[i] + p[i + BB*NVV*HH] + p[i + 2*BB*NVV*HH];
        cv[i] = __float2half(s * rv[i >> 7]);
    }
}

__global__ void rvfin_kernel(const float* __restrict__ sums, float* __restrict__ rv, int n)
{
    int i = blockIdx.x * 256 + threadIdx.x;
    if (i < n) rv[i] = 1.f / (sums[i] + EPSF);
}

__global__ void rowsum_h(const __half* __restrict__ aov, const float* __restrict__ rv,
                         float* __restrict__ to_)
{
    int warp = threadIdx.x >> 5, lane = threadIdx.x & 31;
    int o = blockIdx.x * 8 + warp;
    int b = blockIdx.y;
    if (o >= NOO) return;
    const __half2* row = (const __half2*)(aov + (long)b * NOO * 504 + (long)o * 504);
    const float2* rvb = (const float2*)(rv + b * NVV);
    float s = 0.f;
    #pragma unroll
    for (int i = 0; i < 8; i++) {
        int idx = lane + 32 * i;
        if (idx < 250) {
            float2 f = __half22float2(row[idx]);
            float2 r = rvb[idx];
            s += f.x * r.x + f.y * r.y;
        }
    }
    #pragma unroll
    for (int off = 16; off; off >>= 1) s += __shfl_xor_sync(0xffffffffu, s, off);
    if (lane == 0) to_[b * NOO + o] = 1.f / (s + EPSF);
}

// ---------------- host orchestration ----------------
static GJ mkjob(const __half* A, const __half* Bt, float* Cf, __half* Ch,
                const float* bias, const float* res, const float* rowscale,
                int M, int N, int K, int KpA, int KpB,
                long sA, long sB, long sC, int relu, int nbat)
{
    GJ j;
    j.A = A; j.Bt = Bt; j.Cf = Cf; j.Ch = Ch;
    j.CT = nullptr; j.ldCT = 0; j.Nrow = 1;
    j.s1 = nullptr; j.s2 = nullptr; j.a1 = nullptr; j.a2 = nullptr;
    j.bias = bias; j.res = res; j.rowscale = rowscale;
    j.M = M; j.N = N; j.Ktot = K; j.Ksplit = K;
    j.KpA = KpA; j.KpB = KpB;
    j.sA = sA; j.sB = sB; j.sC = sC;
    j.spA = 0; j.spB = 0; j.spC = 0;
    j.nbat = nbat; j.nsplit = 1; j.relu = relu;
    j.gx = (N + TBN - 1) / TBN;
    j.gy = (M + TBM - 1) / TBM;
    j.total = j.gx * j.gy * nbat;
    return j;
}

static void launch_gemm2(const GJ& a, const GJ& b)
{
    gemm_h<<<a.total + b.total, 256>>>(a, b);
}

extern "C" void kernel_launch(void* const* d_in, const int* in_sizes, int n_in,
                              void* d_out, int out_size)
{
    const float* vis_memory = (const float*)d_in[0];
    const float* obj_memory = (const float*)d_in[1];
    const float* vis_adj    = (const float*)d_in[2];
    const float* obj_adj    = (const float*)d_in[3];
    const float* A_OV       = (const float*)d_in[4];
    const float* Wv1  = (const float*)d_in[5];
    const float* av1a = (const float*)d_in[6];
    const float* av1b = (const float*)d_in[7];
    const float* Wv2  = (const float*)d_in[8];
    const float* av2a = (const float*)d_in[9];
    const float* av2b = (const float*)d_in[10];
    const float* Wo1  = (const float*)d_in[11];
    const float* ao1a = (const float*)d_in[12];
    const float* ao1b = (const float*)d_in[13];
    const float* Wo2  = (const float*)d_in[14];
    const float* ao2a = (const float*)d_in[15];
    const float* ao2b = (const float*)d_in[16];
    const float* g2o_W1 = (const float*)d_in[17];
    const float* g2o_b1 = (const float*)d_in[18];
    const float* g2o_W2 = (const float*)d_in[19];
    const float* g2o_b2 = (const float*)d_in[20];
    const float* o2g_W1 = (const float*)d_in[21];
    const float* o2g_b1 = (const float*)d_in[22];
    const float* o2g_W2 = (const float*)d_in[23];
    const float* o2g_b2 = (const float*)d_in[24];
    const float* img_W = (const float*)d_in[25];
    const float* img_b = (const float*)d_in[26];
    const float* obj_W = (const float*)d_in[27];
    const float* obj_b = (const float*)d_in[28];

    float *p_v, *p_o, *p_cvp, *p_zbuf, *p_rv, *p_to;
    unsigned *p_smax, *p_mv, *p_mo;
    __half *ph_vism, *ph_objm, *ph_aov, *ph_aovt, *ph_oT, *ph_vT, *ph_hvT, *ph_hoT;
    __half *ph_cv, *ph_co, *ph_m1v, *ph_m1o, *ph_vis, *ph_obj, *ph_wt;

    cudaGetSymbolAddress((void**)&p_v,   g_v);
    cudaGetSymbolAddress((void**)&p_o,   g_o);
    cudaGetSymbolAddress((void**)&p_cvp, g_cvp);
    cudaGetSymbolAddress((void**)&p_zbuf, g_zbuf);
    cudaGetSymbolAddress((void**)&p_smax, g_smax);
    cudaGetSymbolAddress((void**)&p_rv,  g_rv);
    cudaGetSymbolAddress((void**)&p_to,  g_to);
    cudaGetSymbolAddress((void**)&p_mv,  g_mv);
    cudaGetSymbolAddress((void**)&p_mo,  g_mo);
    cudaGetSymbolAddress((void**)&ph_vism, h_vism);
    cudaGetSymbolAddress((void**)&ph_objm, h_objm);
    cudaGetSymbolAddress((void**)&ph_aov,  h_aov);
    cudaGetSymbolAddress((void**)&ph_aovt, h_aovt);
    cudaGetSymbolAddress((void**)&ph_oT,   h_oT);
    cudaGetSymbolAddress((void**)&ph_vT,   h_vT);
    cudaGetSymbolAddress((void**)&ph_hvT,  h_hvT);
    cudaGetSymbolAddress((void**)&ph_hoT,  h_hoT);
    cudaGetSymbolAddress((void**)&ph_cv,   h_cv);
    cudaGetSymbolAddress((void**)&ph_co,   h_co);
    cudaGetSymbolAddress((void**)&ph_m1v,  h_m1v);
    cudaGetSymbolAddress((void**)&ph_m1o,  h_m1o);
    cudaGetSymbolAddress((void**)&ph_vis,  h_vis);
    cudaGetSymbolAddress((void**)&ph_obj,  h_obj);
    cudaGetSymbolAddress((void**)&ph_wt,   g_wt);

    float* p_rvsum = p_zbuf;
    float* ps1v = p_zbuf + 4000;
    float* ps2v = p_zbuf + 12000;
    float* ps1o = p_zbuf + 20000;
    float* ps2o = p_zbuf + 44000;

    cudaFuncSetAttribute(attn_h, cudaFuncAttributeMaxDynamicSharedMemorySize, ATTN_SMEM_H);

    // ---- prologue: one memset + one merged prep + rvfin + rowsum ----
    cudaMemsetAsync(p_zbuf, 0, 68000 * sizeof(float));
    {
        WJobs w;
        const float* srcs[10] = { Wv1, Wv2, Wo1, Wo2, o2g_W1, o2g_W2, g2o_W1, g2o_W2, img_W, obj_W };
        int Ks[10] = { 512, 128, 32, 128, 128, 128, 128, 128, 128, 128 };
        int Ns[10] = { 128, 128, 128, 128, 128, 128, 128, 128, 512, 32 };
        long offs[10] = { WT_WV1, WT_WV2, WT_WO1, WT_WO2, WT_O2G1, WT_O2G2,
                          WT_G2O1, WT_G2O2, WT_IMG, WT_OBJ };
        for (int i = 0; i < 10; i++) { w.src[i] = srcs[i]; w.K[i] = Ks[i]; w.N[i] = Ns[i]; w.off[i] = offs[i]; }
        prep<<<NB_PREP, 256>>>(vis_adj, obj_adj, p_mv, p_mo,
                               A_OV, ph_aov, ph_aovt, p_rvsum,
                               vis_memory, ph_vism, obj_memory, ph_objm,
                               w, ph_wt);
    }
    rvfin_kernel<<<(BB * NVV + 255) / 256, 256>>>(p_rvsum, p_rv, BB * NVV);
    rowsum_h<<<dim3((NOO + 7) / 8, BB), 256>>>(ph_aov, p_rv, p_to);

    for (int round = 0; round < 2; round++) {
        const __half* xv = (round == 0) ? ph_vism : ph_vis;
        const __half* xo = (round == 0) ? ph_objm : ph_obj;
        int Kv = (round == 0) ? DVV : HH;
        int Ko = (round == 0) ? DOO : HH;
        const __half* Wvt = ph_wt + ((round == 0) ? WT_WV1 : WT_WV2);
        const __half* Wot = ph_wt + ((round == 0) ? WT_WO1 : WT_WO2);
        const float* ava = (round == 0) ? av1a : av2a;
        const float* avb = (round == 0) ? av1b : av2b;
        const float* aoa = (round == 0) ? ao1a : ao2a;
        const float* aob = (round == 0) ? ao1b : ao2b;
        unsigned* smv = p_smax + (round * 2 + 0) * BB;
        unsigned* smo = p_smax + (round * 2 + 1) * BB;
        float* s1v = ps1v + round * BB * NVV;
        float* s2v = ps2v + round * BB * NVV;
        float* s1o = ps1o + round * BB * NOO;
        float* s2o = ps2o + round * BB * NOO;

        // h = x @ W  (transposed fp16 out + fused scores)
        {
            GJ jv = mkjob(xv, Wvt, nullptr, nullptr, nullptr, nullptr, nullptr,
                          BB * NVV, HH, Kv, Kv, Kv, 0, 0, 0, 0, 1);
            jv.CT = ph_hvT; jv.ldCT = 504; jv.Nrow = NVV;
            jv.s1 = s1v; jv.s2 = s2v; jv.a1 = ava; jv.a2 = avb;
            GJ jo = mkjob(xo, Wot, nullptr, nullptr, nullptr, nullptr, nullptr,
                          BB * NOO, HH, Ko, Ko, Ko, 0, 0, 0, 0, 1);
            jo.CT = ph_hoT; jo.ldCT = 1504; jo.Nrow = NOO;
            jo.s1 = s1o; jo.s2 = s2o; jo.a1 = aoa; jo.a2 = aob;
            launch_gemm2(jv, jo);
        }

        // per-batch max of s2
        smaxk<<<2 * BB, 256>>>(s2v, s2o, smv, smo);

        // attention (fp16 mma, mask-based)
        {
            int nxv = (NVV + AROWS - 1) / AROWS;
            int nxo = (NOO + AROWS - 1) / AROWS;
            AJob av_ = { ph_hvT, s1v, s2v, smv, p_v, ph_vT, p_rv,
                         p_mv, WV, 504, NVV, nxv, nxv * BB };
            AJob ao_ = { ph_hoT, s1o, s2o, smo, p_o, ph_oT, nullptr,
                         p_mo, WO, 1504, NOO, nxo, nxo * BB };
            attn_h<<<av_.total + ao_.total, 256, ATTN_SMEM_H>>>(av_, ao_);
        }

        // cv partials (split-K x3 @512) || co = to ⊙ (A_OV @ (rv⊙v))
        {
            GJ jcv = mkjob(ph_aovt, ph_oT, p_cvp, nullptr, nullptr, nullptr, nullptr,
                           NVV, HH, NOO, 1504, 1504,
                           (long)NVV * 1504, (long)HH * 1504, (long)NVV * HH, 0, BB);
            jcv.Ksplit = 512; jcv.nsplit = 3;
            jcv.spA = 512; jcv.spB = 512; jcv.spC = (long)BB * NVV * HH;
            jcv.total = jcv.gx * jcv.gy * BB * 3;
            GJ jco = mkjob(ph_aov, ph_vT, nullptr, ph_co, nullptr, nullptr, p_to,
                           NOO, HH, NVV, 504, 504,
                           (long)NOO * 504, (long)HH * 504, (long)NOO * HH, 0, BB);
            launch_gemm2(jcv, jco);
        }
        cvred<<<(BB * NVV * HH + 255) / 256, 256>>>(p_cvp, p_rv, ph_cv);

        // mlp layer 1 (relu)
        launch_gemm2(
            mkjob(ph_cv, ph_wt + WT_O2G1, nullptr, ph_m1v, o2g_b1, nullptr, nullptr,
                  BB * NVV, HH, HH, HH, HH, 0, 0, 0, 1, 1),
            mkjob(ph_co, ph_wt + WT_G2O1, nullptr, ph_m1o, g2o_b1, nullptr, nullptr,
                  BB * NOO, HH, HH, HH, HH, 0, 0, 0, 1, 1));

        // mlp layer 2 + residual
        launch_gemm2(
            mkjob(ph_m1v, ph_wt + WT_O2G2, nullptr, ph_vis, o2g_b2, p_v, nullptr,
                  BB * NVV, HH, HH, HH, HH, 0, 0, 0, 0, 1),
            mkjob(ph_m1o, ph_wt + WT_G2O2, nullptr, ph_obj, g2o_b2, p_o, nullptr,
                  BB * NOO, HH, HH, HH, HH, 0, 0, 0, 0, 1));
    }

    // output projections
    float* out_vis = (float*)d_out;
    float* out_obj = out_vis + (long)BB * NVV * DVV;
    launch_gemm2(
        mkjob(ph_vis, ph_wt + WT_IMG, out_vis, nullptr, img_b, nullptr, nullptr,
              BB * NVV, DVV, HH, HH, HH, 0, 0, 0, 0, 1),
        mkjob(ph_obj, ph_wt + WT_OBJ, out_obj, nullptr, obj_b, nullptr, nullptr,
              BB * NOO, DOO, HH, HH, HH, 0, 0, 0, 0, 1));
}

// round 15
// speedup vs baseline: 1.0933x; 1.0098x over previous
#include <cuda_runtime.h>
#include <cuda_fp16.h>
#include <math.h>

#define BB 8
#define NVV 500
#define NOO 1500
#define DVV 512
#define DOO 32
#define HH 128
#define EPSF 1e-5f
#define WV 16
#define WO 48

// ---------------- fp32 scratch ----------------
__device__ float g_cvp[3*BB*NVV*HH];
__device__ float g_zbuf[68000];       // [rvsum 4000][s1v 8000][s2v 8000][s1o 24000][s2o 24000]
__device__ float g_rv  [BB*NVV];
__device__ float g_to  [BB*NOO];
__device__ unsigned g_mv[BB*NVV*WV];
__device__ unsigned g_mo[BB*NOO*WO];

// ---------------- fp16 scratch ----------------
__device__ __half h_vism[BB*NVV*DVV];
__device__ __half h_objm[BB*NOO*DOO];
__device__ __half h_aov [BB*NOO*504];
__device__ __half h_aovt[BB*NVV*1504];
__device__ __half h_oT  [BB*HH*1504];
__device__ __half h_vT  [BB*HH*504];
__device__ __half h_hvT [BB*HH*504 + 32];
__device__ __half h_hoT [BB*HH*1504 + 32];
__device__ __half h_v   [BB*NVV*HH];
__device__ __half h_o   [BB*NOO*HH];
__device__ __half h_cv  [BB*NVV*HH];
__device__ __half h_co  [BB*NOO*HH];
__device__ __half h_m1v [BB*NVV*HH];
__device__ __half h_m1o [BB*NOO*HH];
__device__ __half h_vis [BB*NVV*HH];
__device__ __half h_obj [BB*NOO*HH];
__device__ __half g_wt  [237568];

#define WT_WV1 0
#define WT_WV2 65536
#define WT_WO1 81920
#define WT_WO2 86016
#define WT_O2G1 102400
#define WT_O2G2 118784
#define WT_G2O1 135168
#define WT_G2O2 151552
#define WT_IMG 167936
#define WT_OBJ 233472

// ---------------- helpers ----------------
__device__ __forceinline__ void mma16h(float* d, const unsigned* a, const unsigned* b) {
    asm volatile("mma.sync.aligned.m16n8k16.row.col.f32.f16.f16.f32 "
                 "{%0,%1,%2,%3},{%4,%5,%6,%7},{%8,%9},{%0,%1,%2,%3};"
                 : "+f"(d[0]), "+f"(d[1]), "+f"(d[2]), "+f"(d[3])
                 : "r"(a[0]), "r"(a[1]), "r"(a[2]), "r"(a[3]), "r"(b[0]), "r"(b[1]));
}
__device__ __forceinline__ void cpa16(unsigned dst, const void* src, int srcsz) {
    asm volatile("cp.async.cg.shared.global [%0], [%1], 16, %2;"
                 :: "r"(dst), "l"(src), "r"(srcsz));
}
__device__ __forceinline__ void cpa_commit() {
    asm volatile("cp.async.commit_group;");
}

// ---------------- fp16 GEMM: 64x64 tile, BK=32 halves, 256 threads, 4-stage ----------------
#define TBM 64
#define TBN 64
#define BKH 32
#define TSW 20
#define STAGES 4
#define TILEW (64*TSW)

struct GJ {
    const __half* A; const __half* Bt;
    float* Cf; __half* Ch;
    __half* CT; long ldCT; int Nrow;
    float* s1; float* s2; const float* a1; const float* a2;
    const float* bias; const __half* resh; const float* rowscale;
    int M, N, Ktot, Ksplit;
    int KpA, KpB;
    long sA, sB, sC;
    long spA, spB, spC;
    int nbat, nsplit, relu, gx, gy, total;
};

__device__ __forceinline__ void issue_tile_h(const GJ& j, const __half* Ab, const __half* Bb,
                                             int m0, int n0, int it, int Kact,
                                             unsigned aBase, unsigned bBase, int t)
{
    int row = t >> 2, c = t & 3;
    int gk = it * BKH + c * 8;
    int rem = Kact - gk;
    int sz = rem >= 8 ? 16 : (rem > 0 ? rem * 2 : 0);
    unsigned dstoff = (unsigned)(row * TSW + c * 4) * 4u;
    {
        int gm = m0 + row;
        int s = (gm < j.M) ? sz : 0;
        const __half* src = (gm < j.M) ? &Ab[(long)gm * j.KpA + gk] : Ab;
        cpa16(aBase + dstoff, src, s);
    }
    {
        int gn = n0 + row;
        int s = (gn < j.N) ? sz : 0;
        const __half* src = (gn < j.N) ? &Bb[(long)gn * j.KpB + gk] : Bb;
        cpa16(bBase + dstoff, src, s);
    }
}

__global__ void __launch_bounds__(256) gemm_h(GJ j0, GJ j1)
{
    __shared__ unsigned As[STAGES][TILEW];
    __shared__ unsigned Bs[STAGES][TILEW];

    GJ j; int bid;
    if (blockIdx.x < (unsigned)j0.total) { j = j0; bid = blockIdx.x; }
    else                                 { j = j1; bid = blockIdx.x - j0.total; }

    int per   = j.gx * j.gy;
    int bfull = bid / per;
    int rem   = bid - bfull * per;
    int by    = rem / j.gx;
    int bx    = rem - by * j.gx;
    int s     = bfull / j.nbat;
    int bb    = bfull - s * j.nbat;

    int Kact = j.Ktot - s * j.Ksplit;
    if (Kact > j.Ksplit) Kact = j.Ksplit;

    const __half* Ab = j.A  + (long)bb * j.sA + (long)s * j.spA;
    const __half* Bb = j.Bt + (long)bb * j.sB + (long)s * j.spB;
    long coff = (long)bb * j.sC + (long)s * j.spC;
    int m0 = by * TBM, n0 = bx * TBN;
    int M = j.M, N = j.N;

    int t = threadIdx.x;
    int warp = t >> 5, lane = t & 31;
    int g = lane >> 2, tg = lane & 3;
    int wm = warp >> 1, wn = warp & 1;

    float acc[4][4];
    #pragma unroll
    for (int ni = 0; ni < 4; ni++)
        #pragma unroll
        for (int e = 0; e < 4; e++) acc[ni][e] = 0.f;

    int ntiles = (Kact + BKH - 1) / BKH;

    #pragma unroll
    for (int st = 0; st < STAGES - 1; st++) {
        if (st < ntiles) {
            unsigned aB = (unsigned)__cvta_generic_to_shared(&As[st][0]);
            unsigned bB = (unsigned)__cvta_generic_to_shared(&Bs[st][0]);
            issue_tile_h(j, Ab, Bb, m0, n0, st, Kact, aB, bB, t);
        }
        cpa_commit();
    }

    for (int it = 0; it < ntiles; it++) {
        asm volatile("cp.async.wait_group %0;" :: "n"(STAGES - 2));
        __syncthreads();

        int nx = it + STAGES - 1;
        if (nx < ntiles) {
            unsigned aB = (unsigned)__cvta_generic_to_shared(&As[nx & (STAGES - 1)][0]);
            unsigned bB = (unsigned)__cvta_generic_to_shared(&Bs[nx & (STAGES - 1)][0]);
            issue_tile_h(j, Ab, Bb, m0, n0, nx, Kact, aB, bB, t);
        }
        cpa_commit();

        const unsigned* Asb = As[it & (STAGES - 1)];
        const unsigned* Bsb = Bs[it & (STAGES - 1)];

        #pragma unroll
        for (int kg = 0; kg < 2; kg++) {
            int kw = kg * 8;
            unsigned af[4], bf[4][2];
            int mb = wm * 16 + g;
            af[0] = Asb[mb * TSW + kw + tg];
            af[1] = Asb[(mb + 8) * TSW + kw + tg];
            af[2] = Asb[mb * TSW + kw + tg + 4];
            af[3] = Asb[(mb + 8) * TSW + kw + tg + 4];
            #pragma unroll
            for (int ni = 0; ni < 4; ni++) {
                int nb = wn * 32 + ni * 8 + g;
                bf[ni][0] = Bsb[nb * TSW + kw + tg];
                bf[ni][1] = Bsb[nb * TSW + kw + tg + 4];
            }
            #pragma unroll
            for (int ni = 0; ni < 4; ni++)
                mma16h(acc[ni], af, bf[ni]);
        }
    }

    #pragma unroll
    for (int hf = 0; hf < 2; hf++) {
        int row = m0 + wm * 16 + g + hf * 8;
        bool rok = row < M;
        float p1 = 0.f, p2 = 0.f;
        if (rok) {
            float scale = j.rowscale ? j.rowscale[bb * M + row] : 1.f;
            // hoisted CT index math (one div per row, not per frag)
            long tb0 = 0;
            if (j.CT) {
                int b2 = row / j.Nrow;
                int n2 = row - b2 * j.Nrow;
                tb0 = (long)b2 * HH * j.ldCT + n2;
            }
            long rowoff = coff + (long)row * N;
            #pragma unroll
            for (int ni = 0; ni < 4; ni++) {
                int col = n0 + wn * 32 + ni * 8 + tg * 2;
                if (col >= N) continue;
                float v0 = acc[ni][hf * 2 + 0] * scale;
                float v1 = acc[ni][hf * 2 + 1] * scale;
                if (j.bias) { v0 += j.bias[col]; v1 += j.bias[col + 1]; }
                long off = rowoff + col;
                if (j.resh) {
                    __half2 r = *(const __half2*)&j.resh[off];
                    float2 rf = __half22float2(r);
                    v0 += rf.x; v1 += rf.y;
                }
                if (j.relu) { v0 = v0 > 0.f ? v0 : 0.f; v1 = v1 > 0.f ? v1 : 0.f; }
                if (j.Cf) *(float2*)&j.Cf[off] = make_float2(v0, v1);
                if (j.Ch) *(__half2*)&j.Ch[off] = __floats2half2_rn(v0, v1);
                if (j.CT) {
                    long tb = tb0 + (long)col * j.ldCT;
                    j.CT[tb] = __float2half(v0);
                    j.CT[tb + j.ldCT] = __float2half(v1);
                }
                if (j.s1) {
                    p1 += v0 * j.a1[col] + v1 * j.a1[col + 1];
                    p2 += v0 * j.a2[col] + v1 * j.a2[col + 1];
                }
            }
        }
        if (j.s1) {
            p1 += __shfl_down_sync(0xffffffffu, p1, 2);
            p1 += __shfl_down_sync(0xffffffffu, p1, 1);
            p2 += __shfl_down_sync(0xffffffffu, p2, 2);
            p2 += __shfl_down_sync(0xffffffffu, p2, 1);
            if (tg == 0 && rok) {
                atomicAdd(&j.s1[row], p1);
                atomicAdd(&j.s2[row], p2);
            }
        }
    }
}

// ---------------- merged prologue: maskbuild | aovprep | cvtflat x2 | wcvt ----------------
#define NB_MASK 2000
#define NB_AOV  (16*47*BB)
#define NB_CVV  2000
#define NB_CVO  375
#define NB_W    640
#define NB_PREP (NB_MASK + NB_AOV + NB_CVV + NB_CVO + NB_W)

struct WJobs { const float* src[10]; int K[10]; int N[10]; long off[10]; };

__global__ void __launch_bounds__(256) prep(
    const float* __restrict__ adjv, const float* __restrict__ adjo,
    unsigned* __restrict__ mv, unsigned* __restrict__ mo,
    const float* __restrict__ Aov, __half* __restrict__ aov,
    __half* __restrict__ aovt, float* __restrict__ csum,
    const float* __restrict__ vism, __half* __restrict__ vismh,
    const float* __restrict__ objm, __half* __restrict__ objmh,
    WJobs w, __half* __restrict__ arena)
{
    __shared__ float tl[32][33];
    int bidx = blockIdx.x;
    int tid = threadIdx.x;

    if (bidx < NB_MASK) {
        int warp = tid >> 5, lane = tid & 31;
        long gw = (long)bidx * 8 + warp;
        const float* adj; unsigned* m; int N, W; long row;
        if (gw < (long)BB * NVV) { adj = adjv; m = mv; N = NVV; W = WV; row = gw; }
        else                     { adj = adjo; m = mo; N = NOO; W = WO; row = gw - (long)BB * NVV; }
        const float* ar = adj + row * (long)N;
        unsigned* mr = m + row * (long)W;
        int nit = (W + 3) / 4;
        for (int it = 0; it < nit; it++) {
            int j0 = it * 128 + lane * 4;
            unsigned nib = 0;
            if (j0 + 3 < N) {
                float4 a = *(const float4*)&ar[j0];
                if (a.x > 0.f) nib |= 1u;
                if (a.y > 0.f) nib |= 2u;
                if (a.z > 0.f) nib |= 4u;
                if (a.w > 0.f) nib |= 8u;
            } else {
                #pragma unroll
                for (int e = 0; e < 4; e++)
                    if (j0 + e < N && ar[j0 + e] > 0.f) nib |= 1u << e;
            }
            unsigned v = nib << ((lane & 7) * 4);
            v |= __shfl_xor_sync(0xffffffffu, v, 1);
            v |= __shfl_xor_sync(0xffffffffu, v, 2);
            v |= __shfl_xor_sync(0xffffffffu, v, 4);
            if ((lane & 7) == 0) {
                int ww = it * 4 + (lane >> 3);
                if (ww < W) mr[ww] = v;
            }
        }
        return;
    }
    bidx -= NB_MASK;
    if (bidx < NB_AOV) {
        int b = bidx / (16 * 47);
        int r2 = bidx - b * (16 * 47);
        int yb = r2 / 16;
        int xb = r2 - yb * 16;
        int v0 = xb * 32, o0 = yb * 32;
        int tx = tid & 31, ty = tid >> 5;
        const float* Ab = Aov + (long)b * NOO * NVV;
        #pragma unroll
        for (int i = 0; i < 4; i++) {
            int o = o0 + ty + i * 8, v = v0 + tx;
            tl[ty + i * 8][tx] = (o < NOO && v < NVV) ? Ab[(long)o * NVV + v] : 0.f;
        }
        __syncthreads();
        #pragma unroll
        for (int i = 0; i < 4; i++) {
            int o = o0 + ty + i * 8, v = v0 + tx;
            if (o < NOO && v < 504)
                aov[(long)b * NOO * 504 + (long)o * 504 + v] = __float2half(tl[ty + i * 8][tx]);
        }
        #pragma unroll
        for (int i = 0; i < 4; i++) {
            int v = v0 + ty + i * 8, o = o0 + tx;
            if (v < NVV)
                aovt[(long)b * NVV * 1504 + (long)v * 1504 + o] = __float2half(tl[tx][ty + i * 8]);
        }
        if (ty == 0 && v0 + tx < NVV) {
            float s = 0.f;
            #pragma unroll
            for (int o = 0; o < 32; o++) s += tl[o][tx];
            atomicAdd(&csum[b * NVV + v0 + tx], s);
        }
        return;
    }
    bidx -= NB_AOV;
    if (bidx < NB_CVV + NB_CVO) {
        const float* src; __half* dst; long n4; long i0;
        if (bidx < NB_CVV) { src = vism; dst = vismh; n4 = (long)BB * NVV * DVV / 4; i0 = (long)bidx * 256; }
        else { src = objm; dst = objmh; n4 = (long)BB * NOO * DOO / 4; i0 = (long)(bidx - NB_CVV) * 256; }
        long i = i0 + tid;
        if (i < n4) {
            float4 v = *(const float4*)&src[i * 4];
            __half2 h0 = __floats2half2_rn(v.x, v.y);
            __half2 h1 = __floats2half2_rn(v.z, v.w);
            uint2 u;
            u.x = *(unsigned*)&h0;
            u.y = *(unsigned*)&h1;
            *(uint2*)&dst[i * 4] = u;
        }
        return;
    }
    bidx -= NB_CVV + NB_CVO;
    {
        int jid = bidx / 64;
        int xb = bidx - jid * 64;
        const float* s = w.src[jid];
        int K = w.K[jid], N = w.N[jid];
        long off = w.off[jid];
        long n = (long)K * N;
        for (long idx = (long)xb * 256 + tid; idx < n; idx += 64L * 256) {
            long k = idx / N;
            int c = (int)(idx - k * N);
            arena[off + (long)c * K + k] = __float2half(s[idx]);
        }
    }
}

// ---------------- fp16 fused masked-softmax attention (self-contained smax) ----------------
#define AROWS 64
#define AJC 128
#define HS2 68
#define ATTN_SMEM_H ((128*HS2 + AROWS*HS2 + AROWS + 256) * 4)

struct AJob {
    const __half* hT; const float* s1; const float* s2;
    __half* out; __half* outT; const float* tsc;
    const unsigned* mask; int W;
    long ldT; int N; int nx; int total;
};

__global__ void __launch_bounds__(256) attn_h(AJob j0, AJob j1)
{
    extern __shared__ unsigned smu[];
    unsigned* hsT = smu;
    unsigned* wsh = smu + 128 * HS2;
    float* zrow   = (float*)(wsh + AROWS * HS2);
    float* redm   = zrow + AROWS;

    AJob j; int bid;
    if (blockIdx.x < (unsigned)j0.total) { j = j0; bid = blockIdx.x; }
    else                                 { j = j1; bid = blockIdx.x - j0.total; }
    int b  = bid / j.nx;
    int i0 = (bid - b * j.nx) * AROWS;
    int N  = j.N;

    int t = threadIdx.x;
    int warp = t >> 5, lane = t & 31;
    int g = lane >> 2, tg = lane & 3;
    int wm = warp >> 2, wn = warp & 3;

    const __half* hTb  = j.hT + (long)b * HH * j.ldT;
    const float* s2b   = j.s2  + (long)b * N;
    unsigned hsBase = (unsigned)__cvta_generic_to_shared(hsT);

    // per-block smax of s2 (replaces smaxk kernel)
    {
        float m = -1e30f;
        for (int i = t; i < N; i += 256) m = fmaxf(m, s2b[i]);
        redm[t] = m;
        __syncthreads();
        #pragma unroll
        for (int s = 128; s > 0; s >>= 1) {
            if (t < s) redm[t] = fmaxf(redm[t], redm[t + s]);
            __syncthreads();
        }
    }
    float mb = redm[0];

    float acc[2][4][4];
    #pragma unroll
    for (int mi = 0; mi < 2; mi++)
        #pragma unroll
        for (int ni = 0; ni < 4; ni++)
            #pragma unroll
            for (int e = 0; e < 4; e++) acc[mi][ni][e] = 0.f;

    if (t < AROWS) zrow[t] = 0.f;

    int pr = t >> 2;
    int pj = (t & 3) * 32;
    int prow = i0 + pr;
    float s1r = 0.f, mrow = 0.f;
    if (prow < N) {
        s1r = j.s1[(long)b * N + prow];
        float x = s1r + mb;
        mrow = x > 0.f ? x : 0.2f * x;
    }

    int sf = t >> 1;
    int ss = (t & 1) * 64;

    for (int c0 = 0; c0 < N; c0 += AJC) {
        __syncthreads();

        {
            const __half* src = hTb + (long)sf * j.ldT + c0 + ss;
            unsigned dst = hsBase + (unsigned)(sf * HS2) * 4u + (unsigned)ss * 2u;
            #pragma unroll
            for (int s = 0; s < 8; s++)
                cpa16(dst + s * 16u, src + s * 8, 16);
            cpa_commit();
        }

        float zl = 0.f;
        if (prow < N) {
            long mbase = ((long)b * N + prow) * j.W + (c0 >> 5) + (t & 3);
            int wbase = pr * HS2 + (pj >> 1);
            unsigned mw = j.mask[mbase];
            if (mw) {
                #pragma unroll
                for (int q4 = 0; q4 < 32; q4 += 4) {
                    int jj = pj + q4;
                    int gj = c0 + jj;
                    float sv[4];
                    if (gj + 3 < N) {
                        float4 s4 = *(const float4*)&s2b[gj];
                        sv[0]=s4.x; sv[1]=s4.y; sv[2]=s4.z; sv[3]=s4.w;
                    } else {
                        #pragma unroll
                        for (int e = 0; e < 4; e++)
                            sv[e] = (gj + e) < N ? s2b[gj + e] : 0.f;
                    }
                    float w[4];
                    #pragma unroll
                    for (int e = 0; e < 4; e++) {
                        w[e] = 0.f;
                        if ((mw >> (q4 + e)) & 1u) {
                            float x = s1r + sv[e];
                            float ev = x > 0.f ? x : 0.2f * x;
                            w[e] = __expf(ev - mrow);
                        }
                    }
                    __half2 u0 = __floats2half2_rn(w[0], w[1]);
                    __half2 u1 = __floats2half2_rn(w[2], w[3]);
                    *(__half2*)&wsh[wbase + (q4 >> 1)]     = u0;
                    *(__half2*)&wsh[wbase + (q4 >> 1) + 1] = u1;
                    float2 f0 = __half22float2(u0), f1 = __half22float2(u1);
                    zl += f0.x + f0.y + f1.x + f1.y;
                }
            } else {
                #pragma unroll
                for (int q = 0; q < 16; q++) wsh[wbase + q] = 0u;
            }
        } else {
            int wbase = pr * HS2 + (pj >> 1);
            #pragma unroll
            for (int q = 0; q < 16; q++) wsh[wbase + q] = 0u;
        }
        zl += __shfl_down_sync(0xffffffffu, zl, 2);
        zl += __shfl_down_sync(0xffffffffu, zl, 1);
        if ((t & 3) == 0 && prow < N) zrow[pr] += zl;

        asm volatile("cp.async.wait_group 0;");
        __syncthreads();

        #pragma unroll
        for (int kg = 0; kg < 8; kg++) {
            int kw = kg * 8;
            unsigned af[2][4], bf[4][2];
            #pragma unroll
            for (int mi = 0; mi < 2; mi++) {
                int mr = wm * 32 + mi * 16 + g;
                af[mi][0] = wsh[mr * HS2 + kw + tg];
                af[mi][1] = wsh[(mr + 8) * HS2 + kw + tg];
                af[mi][2] = wsh[mr * HS2 + kw + tg + 4];
                af[mi][3] = wsh[(mr + 8) * HS2 + kw + tg + 4];
            }
            #pragma unroll
            for (int ni = 0; ni < 4; ni++) {
                int nr = wn * 32 + ni * 8 + g;
                bf[ni][0] = hsT[nr * HS2 + kw + tg];
                bf[ni][1] = hsT[nr * HS2 + kw + tg + 4];
            }
            #pragma unroll
            for (int mi = 0; mi < 2; mi++)
                #pragma unroll
                for (int ni = 0; ni < 4; ni++)
                    mma16h(acc[mi][ni], af[mi], bf[ni]);
        }
    }
    __syncthreads();

    long tbb = (long)b * HH * j.ldT;
    #pragma unroll
    for (int mi = 0; mi < 2; mi++) {
        #pragma unroll
        for (int hf = 0; hf < 2; hf++) {
            int r0 = wm * 32 + mi * 16 + g + hf * 8;
            int row = i0 + r0;
            if (row >= N) continue;
            float inv = 1.f / zrow[r0];
            float rs = j.tsc ? j.tsc[(long)b * N + row] : 1.f;
            long tb0 = tbb + row;
            #pragma unroll
            for (int ni = 0; ni < 4; ni++) {
                int col = wn * 32 + ni * 8 + tg * 2;
                float v0 = acc[mi][ni][hf * 2 + 0] * inv;
                float v1 = acc[mi][ni][hf * 2 + 1] * inv;
                v0 = v0 > 0.f ? v0 : 0.f;
                v1 = v1 > 0.f ? v1 : 0.f;
                long off = (long)b * N * HH + (long)row * HH + col;
                *(__half2*)&j.out[off] = __floats2half2_rn(v0, v1);
                j.outT[tb0 + (long)col * j.ldT]       = __float2half(v0 * rs);
                j.outT[tb0 + (long)(col + 1) * j.ldT] = __float2half(v1 * rs);
            }
        }
    }
}

// ---------------- remaining helpers ----------------
__global__ void cvred(const float* __restrict__ p, const float* __restrict__ rv,
                      __half* __restrict__ cv)
{
    int i = blockIdx.x * 256 + threadIdx.x;
    if (i < BB * NVV * HH) {
        float s = p[i] + p[i + BB*NVV*HH] + p[i + 2*BB*NVV*HH];
        cv[i] = __float2half(s * rv[i >> 7]);
    }
}

__global__ void rvfin_kernel(const float* __restrict__ sums, float* __restrict__ rv, int n)
{
    int i = blockIdx.x * 256 + threadIdx.x;
    if (i < n) rv[i] = 1.f / (sums[i] + EPSF);
}

__global__ void rowsum_h(const __half* __restrict__ aov, const float* __restrict__ rv,
                         float* __restrict__ to_)
{
    int warp = threadIdx.x >> 5, lane = threadIdx.x & 31;
    int o = blockIdx.x * 8 + warp;
    int b = blockIdx.y;
    if (o >= NOO) return;
    const __half2* row = (const __half2*)(aov + (long)b * NOO * 504 + (long)o * 504);
    const float2* rvb = (const float2*)(rv + b * NVV);
    float s = 0.f;
    #pragma unroll
    for (int i = 0; i < 8; i++) {
        int idx = lane + 32 * i;
        if (idx < 250) {
            float2 f = __half22float2(row[idx]);
            float2 r = rvb[idx];
            s += f.x * r.x + f.y * r.y;
        }
    }
    #pragma unroll
    for (int off = 16; off; off >>= 1) s += __shfl_xor_sync(0xffffffffu, s, off);
    if (lane == 0) to_[b * NOO + o] = 1.f / (s + EPSF);
}

// ---------------- host orchestration ----------------
static GJ mkjob(const __half* A, const __half* Bt, float* Cf, __half* Ch,
                const float* bias, const __half* resh, const float* rowscale,
                int M, int N, int K, int KpA, int KpB,
                long sA, long sB, long sC, int relu, int nbat)
{
    GJ j;
    j.A = A; j.Bt = Bt; j.Cf = Cf; j.Ch = Ch;
    j.CT = nullptr; j.ldCT = 0; j.Nrow = 1;
    j.s1 = nullptr; j.s2 = nullptr; j.a1 = nullptr; j.a2 = nullptr;
    j.bias = bias; j.resh = resh; j.rowscale = rowscale;
    j.M = M; j.N = N; j.Ktot = K; j.Ksplit = K;
    j.KpA = KpA; j.KpB = KpB;
    j.sA = sA; j.sB = sB; j.sC = sC;
    j.spA = 0; j.spB = 0; j.spC = 0;
    j.nbat = nbat; j.nsplit = 1; j.relu = relu;
    j.gx = (N + TBN - 1) / TBN;
    j.gy = (M + TBM - 1) / TBM;
    j.total = j.gx * j.gy * nbat;
    return j;
}

static void launch_gemm2(const GJ& a, const GJ& b)
{
    gemm_h<<<a.total + b.total, 256>>>(a, b);
}

extern "C" void kernel_launch(void* const* d_in, const int* in_sizes, int n_in,
                              void* d_out, int out_size)
{
    const float* vis_memory = (const float*)d_in[0];
    const float* obj_memory = (const float*)d_in[1];
    const float* vis_adj    = (const float*)d_in[2];
    const float* obj_adj    = (const float*)d_in[3];
    const float* A_OV       = (const float*)d_in[4];
    const float* Wv1  = (const float*)d_in[5];
    const float* av1a = (const float*)d_in[6];
    const float* av1b = (const float*)d_in[7];
    const float* Wv2  = (const float*)d_in[8];
    const float* av2a = (const float*)d_in[9];
    const float* av2b = (const float*)d_in[10];
    const float* Wo1  = (const float*)d_in[11];
    const float* ao1a = (const float*)d_in[12];
    const float* ao1b = (const float*)d_in[13];
    const float* Wo2  = (const float*)d_in[14];
    const float* ao2a = (const float*)d_in[15];
    const float* ao2b = (const float*)d_in[16];
    const float* g2o_W1 = (const float*)d_in[17];
    const float* g2o_b1 = (const float*)d_in[18];
    const float* g2o_W2 = (const float*)d_in[19];
    const float* g2o_b2 = (const float*)d_in[20];
    const float* o2g_W1 = (const float*)d_in[21];
    const float* o2g_b1 = (const float*)d_in[22];
    const float* o2g_W2 = (const float*)d_in[23];
    const float* o2g_b2 = (const float*)d_in[24];
    const float* img_W = (const float*)d_in[25];
    const float* img_b = (const float*)d_in[26];
    const float* obj_W = (const float*)d_in[27];
    const float* obj_b = (const float*)d_in[28];

    float *p_cvp, *p_zbuf, *p_rv, *p_to;
    unsigned *p_mv, *p_mo;
    __half *ph_vism, *ph_objm, *ph_aov, *ph_aovt, *ph_oT, *ph_vT, *ph_hvT, *ph_hoT;
    __half *ph_v, *ph_o, *ph_cv, *ph_co, *ph_m1v, *ph_m1o, *ph_vis, *ph_obj, *ph_wt;

    cudaGetSymbolAddress((void**)&p_cvp, g_cvp);
    cudaGetSymbolAddress((void**)&p_zbuf, g_zbuf);
    cudaGetSymbolAddress((void**)&p_rv,  g_rv);
    cudaGetSymbolAddress((void**)&p_to,  g_to);
    cudaGetSymbolAddress((void**)&p_mv,  g_mv);
    cudaGetSymbolAddress((void**)&p_mo,  g_mo);
    cudaGetSymbolAddress((void**)&ph_vism, h_vism);
    cudaGetSymbolAddress((void**)&ph_objm, h_objm);
    cudaGetSymbolAddress((void**)&ph_aov,  h_aov);
    cudaGetSymbolAddress((void**)&ph_aovt, h_aovt);
    cudaGetSymbolAddress((void**)&ph_oT,   h_oT);
    cudaGetSymbolAddress((void**)&ph_vT,   h_vT);
    cudaGetSymbolAddress((void**)&ph_hvT,  h_hvT);
    cudaGetSymbolAddress((void**)&ph_hoT,  h_hoT);
    cudaGetSymbolAddress((void**)&ph_v,    h_v);
    cudaGetSymbolAddress((void**)&ph_o,    h_o);
    cudaGetSymbolAddress((void**)&ph_cv,   h_cv);
    cudaGetSymbolAddress((void**)&ph_co,   h_co);
    cudaGetSymbolAddress((void**)&ph_m1v,  h_m1v);
    cudaGetSymbolAddress((void**)&ph_m1o,  h_m1o);
    cudaGetSymbolAddress((void**)&ph_vis,  h_vis);
    cudaGetSymbolAddress((void**)&ph_obj,  h_obj);
    cudaGetSymbolAddress((void**)&ph_wt,   g_wt);

    float* p_rvsum = p_zbuf;
    float* ps1v = p_zbuf + 4000;
    float* ps2v = p_zbuf + 12000;
    float* ps1o = p_zbuf + 20000;
    float* ps2o = p_zbuf + 44000;

    cudaFuncSetAttribute(attn_h, cudaFuncAttributeMaxDynamicSharedMemorySize, ATTN_SMEM_H);

    // ---- prologue ----
    cudaMemsetAsync(p_zbuf, 0, 68000 * sizeof(float));
    {
        WJobs w;
        const float* srcs[10] = { Wv1, Wv2, Wo1, Wo2, o2g_W1, o2g_W2, g2o_W1, g2o_W2, img_W, obj_W };
        int Ks[10] = { 512, 128, 32, 128, 128, 128, 128, 128, 128, 128 };
        int Ns[10] = { 128, 128, 128, 128, 128, 128, 128, 128, 512, 32 };
        long offs[10] = { WT_WV1, WT_WV2, WT_WO1, WT_WO2, WT_O2G1, WT_O2G2,
                          WT_G2O1, WT_G2O2, WT_IMG, WT_OBJ };
        for (int i = 0; i < 10; i++) { w.src[i] = srcs[i]; w.K[i] = Ks[i]; w.N[i] = Ns[i]; w.off[i] = offs[i]; }
        prep<<<NB_PREP, 256>>>(vis_adj, obj_adj, p_mv, p_mo,
                               A_OV, ph_aov, ph_aovt, p_rvsum,
                               vis_memory, ph_vism, obj_memory, ph_objm,
                               w, ph_wt);
    }
    rvfin_kernel<<<(BB * NVV + 255) / 256, 256>>>(p_rvsum, p_rv, BB * NVV);
    rowsum_h<<<dim3((NOO + 7) / 8, BB), 256>>>(ph_aov, p_rv, p_to);

    for (int round = 0; round < 2; round++) {
        const __half* xv = (round == 0) ? ph_vism : ph_vis;
        const __half* xo = (round == 0) ? ph_objm : ph_obj;
        int Kv = (round == 0) ? DVV : HH;
        int Ko = (round == 0) ? DOO : HH;
        const __half* Wvt = ph_wt + ((round == 0) ? WT_WV1 : WT_WV2);
        const __half* Wot = ph_wt + ((round == 0) ? WT_WO1 : WT_WO2);
        const float* ava = (round == 0) ? av1a : av2a;
        const float* avb = (round == 0) ? av1b : av2b;
        const float* aoa = (round == 0) ? ao1a : ao2a;
        const float* aob = (round == 0) ? ao1b : ao2b;
        float* s1v = ps1v + round * BB * NVV;
        float* s2v = ps2v + round * BB * NVV;
        float* s1o = ps1o + round * BB * NOO;
        float* s2o = ps2o + round * BB * NOO;

        // h = x @ W  (transposed fp16 out + fused scores)
        {
            GJ jv = mkjob(xv, Wvt, nullptr, nullptr, nullptr, nullptr, nullptr,
                          BB * NVV, HH, Kv, Kv, Kv, 0, 0, 0, 0, 1);
            jv.CT = ph_hvT; jv.ldCT = 504; jv.Nrow = NVV;
            jv.s1 = s1v; jv.s2 = s2v; jv.a1 = ava; jv.a2 = avb;
            GJ jo = mkjob(xo, Wot, nullptr, nullptr, nullptr, nullptr, nullptr,
                          BB * NOO, HH, Ko, Ko, Ko, 0, 0, 0, 0, 1);
            jo.CT = ph_hoT; jo.ldCT = 1504; jo.Nrow = NOO;
            jo.s1 = s1o; jo.s2 = s2o; jo.a1 = aoa; jo.a2 = aob;
            launch_gemm2(jv, jo);
        }

        // attention (fp16 mma, mask-based, self-computed smax); obj job first (long blocks)
        {
            int nxv = (NVV + AROWS - 1) / AROWS;
            int nxo = (NOO + AROWS - 1) / AROWS;
            AJob ao_ = { ph_hoT, s1o, s2o, ph_o, ph_oT, nullptr,
                         p_mo, WO, 1504, NOO, nxo, nxo * BB };
            AJob av_ = { ph_hvT, s1v, s2v, ph_v, ph_vT, p_rv,
                         p_mv, WV, 504, NVV, nxv, nxv * BB };
            attn_h<<<ao_.total + av_.total, 256, ATTN_SMEM_H>>>(ao_, av_);
        }

        // cv partials (split-K x3 @512) || co = to ⊙ (A_OV @ (rv⊙v))
        {
            GJ jcv = mkjob(ph_aovt, ph_oT, p_cvp, nullptr, nullptr, nullptr, nullptr,
                           NVV, HH, NOO, 1504, 1504,
                           (long)NVV * 1504, (long)HH * 1504, (long)NVV * HH, 0, BB);
            jcv.Ksplit = 512; jcv.nsplit = 3;
            jcv.spA = 512; jcv.spB = 512; jcv.spC = (long)BB * NVV * HH;
            jcv.total = jcv.gx * jcv.gy * BB * 3;
            GJ jco = mkjob(ph_aov, ph_vT, nullptr, ph_co, nullptr, nullptr, p_to,
                           NOO, HH, NVV, 504, 504,
                           (long)NOO * 504, (long)HH * 504, (long)NOO * HH, 0, BB);
            launch_gemm2(jcv, jco);
        }
        cvred<<<(BB * NVV * HH + 255) / 256, 256>>>(p_cvp, p_rv, ph_cv);

        // mlp layer 1 (relu)
        launch_gemm2(
            mkjob(ph_cv, ph_wt + WT_O2G1, nullptr, ph_m1v, o2g_b1, nullptr, nullptr,
                  BB * NVV, HH, HH, HH, HH, 0, 0, 0, 1, 1),
            mkjob(ph_co, ph_wt + WT_G2O1, nullptr, ph_m1o, g2o_b1, nullptr, nullptr,
                  BB * NOO, HH, HH, HH, HH, 0, 0, 0, 1, 1));

        // mlp layer 2 + fp16 residual
        launch_gemm2(
            mkjob(ph_m1v, ph_wt + WT_O2G2, nullptr, ph_vis, o2g_b2, ph_v, nullptr,
                  BB * NVV, HH, HH, HH, HH, 0, 0, 0, 0, 1),
            mkjob(ph_m1o, ph_wt + WT_G2O2, nullptr, ph_obj, g2o_b2, ph_o, nullptr,
                  BB * NOO, HH, HH, HH, HH, 0, 0, 0, 0, 1));
    }

    // output projections
    float* out_vis = (float*)d_out;
    float* out_obj = out_vis + (long)BB * NVV * DVV;
    launch_gemm2(
        mkjob(ph_vis, ph_wt + WT_IMG, out_vis, nullptr, img_b, nullptr, nullptr,
              BB * NVV, DVV, HH, HH, HH, 0, 0, 0, 0, 1),
        mkjob(ph_obj, ph_wt + WT_OBJ, out_obj, nullptr, obj_b, nullptr, nullptr,
              BB * NOO, DOO, HH, HH, HH, 0, 0, 0, 0, 1));
}